// round 13
// baseline (speedup 1.0000x reference)
#include <cuda_runtime.h>
#include <cuda_bf16.h>
#include <cstdint>

// Problem constants
#define B_SZ   4096
#define DIN    768
#define DOUT   512
#define Q_SZ   64
#define H1_SZ  32
#define H2_SZ  64
#define EPS    1e-5f

// GEMM1 split-K: K' = 3 * DIN, A duplicated [hi|hi|lo]
#define KSPLIT (3 * DIN)          // 2304
#define KC     64
#define NCHH   (KSPLIT / KC / 2)  // 18 chunks per K-half
#define GS     3
#define TILEB  16384
#define STAGEB (2 * TILEB)

// kan stage-E mma: K2 = 3*H2 = 192, 12 chunks of k16
#define K2     192
#define NKC2   12

// ---------------------------------------------------------------------------
// Static device scratch
// ---------------------------------------------------------------------------
__device__ __align__(256) float          g_xp[2][B_SZ * DOUT];          // 16 MB partials
__device__ __align__(256) __nv_bfloat16  g_A[B_SZ * KSPLIT];            // 18.9 MB
__device__ __align__(256) __nv_bfloat16  g_Bt[DOUT * KSPLIT];           // 2.36 MB
__device__ __align__(256) __nv_bfloat16  g_B2[NKC2 * DOUT * 16];        // 196 KB (k-blocked wo2')

// ---------------------------------------------------------------------------
// Helpers
// ---------------------------------------------------------------------------
__device__ __forceinline__ uint32_t smem_u32(const void* p) {
    uint32_t a;
    asm("{ .reg .u64 t; cvta.to.shared.u64 t, %1; cvt.u32.u64 %0, t; }"
        : "=r"(a) : "l"(p));
    return a;
}
__device__ __forceinline__ uint32_t swz(uint32_t off) {
    return off ^ ((off >> 3) & 0x70);
}
__device__ __forceinline__ void cpasync16(uint32_t dst, const void* src) {
    asm volatile("cp.async.cg.shared.global [%0], [%1], 16;"
                 :: "r"(dst), "l"(src) : "memory");
}
__device__ __forceinline__ void ldsm_x4(uint32_t* r, uint32_t addr) {
    asm volatile("ldmatrix.sync.aligned.m8n8.x4.shared.b16 {%0,%1,%2,%3}, [%4];"
                 : "=r"(r[0]), "=r"(r[1]), "=r"(r[2]), "=r"(r[3]) : "r"(addr));
}
__device__ __forceinline__ void mma16816(float* d, const uint32_t* a, const uint32_t* b) {
    asm volatile(
        "mma.sync.aligned.m16n8k16.row.col.f32.bf16.bf16.f32 "
        "{%0,%1,%2,%3}, {%4,%5,%6,%7}, {%8,%9}, {%0,%1,%2,%3};"
        : "+f"(d[0]), "+f"(d[1]), "+f"(d[2]), "+f"(d[3])
        : "r"(a[0]), "r"(a[1]), "r"(a[2]), "r"(a[3]), "r"(b[0]), "r"(b[1]));
}

// ---- packed f32x2 ----
__device__ __forceinline__ uint64_t pk2(float x, float y) {
    uint64_t r; asm("mov.b64 %0,{%1,%2};" : "=l"(r) : "f"(x), "f"(y)); return r;
}
__device__ __forceinline__ void upk2(uint64_t v, float& x, float& y) {
    asm("mov.b64 {%0,%1},%2;" : "=f"(x), "=f"(y) : "l"(v));
}
__device__ __forceinline__ uint64_t fma2(uint64_t a, uint64_t b, uint64_t c) {
    uint64_t d; asm("fma.rn.f32x2 %0,%1,%2,%3;" : "=l"(d) : "l"(a), "l"(b), "l"(c));
    return d;
}
__device__ __forceinline__ uint64_t add2(uint64_t a, uint64_t b) {
    uint64_t d; asm("add.rn.f32x2 %0,%1,%2;" : "=l"(d) : "l"(a), "l"(b));
    return d;
}
__device__ __forceinline__ uint64_t abs2(uint64_t a) {
    uint64_t d; asm("and.b64 %0,%1,0x7FFFFFFF7FFFFFFF;" : "=l"(d) : "l"(a));
    return d;
}

// ---------------------------------------------------------------------------
// Conversions
// ---------------------------------------------------------------------------
__global__ void __launch_bounds__(256)
conv_x(const float* __restrict__ x, __nv_bfloat16* __restrict__ A)
{
    const int row = blockIdx.x;
    const float* xr = x + (long)row * DIN;
    __nv_bfloat16* Ar = A + (long)row * KSPLIT;
    #pragma unroll
    for (int i = 0; i < 3; i++) {
        const int k = threadIdx.x + i * 256;
        const float v = xr[k];
        const __nv_bfloat16 hi = __float2bfloat16(v);
        const __nv_bfloat16 lo = __float2bfloat16(v - __bfloat162float(hi));
        Ar[k]            = hi;
        Ar[k + DIN]      = hi;
        Ar[k + 2 * DIN]  = lo;
    }
}

__global__ void __launch_bounds__(256)
conv_w(const float* __restrict__ wp, __nv_bfloat16* __restrict__ Bt)
{
    __shared__ float t[32][33];
    const int k0 = blockIdx.x * 32, n0 = blockIdx.y * 32;
    const int tx = threadIdx.x & 31;
    const int ty = threadIdx.x >> 5;
    #pragma unroll
    for (int dy = 0; dy < 32; dy += 8)
        t[ty + dy][tx] = wp[(long)(k0 + ty + dy) * DOUT + n0 + tx];
    __syncthreads();
    #pragma unroll
    for (int dy = 0; dy < 32; dy += 8) {
        const int n = n0 + ty + dy, k = k0 + tx;
        const float v = t[tx][ty + dy];
        const __nv_bfloat16 hi = __float2bfloat16(v);
        const __nv_bfloat16 lo = __float2bfloat16(v - __bfloat162float(hi));
        __nv_bfloat16* Br = Bt + (long)n * KSPLIT;
        Br[k]           = hi;
        Br[k + DIN]     = lo;
        Br[k + 2 * DIN] = hi;
    }
}

// wo2 [H2=64, DOUT] fp32 -> B2 blocked [kc][n][kk] bf16, K2 regions:
// k<64 -> hi(w[k][n]); 64..127 -> lo(w[k-64][n]); 128..191 -> hi(w[k-128][n])
__global__ void __launch_bounds__(256)
conv_wo2(const float* __restrict__ wo2, __nv_bfloat16* __restrict__ B2)
{
    const int n = blockIdx.x * 256 + threadIdx.x;
    #pragma unroll 4
    for (int h = 0; h < H2_SZ; h++) {
        const float v = wo2[h * DOUT + n];
        const __nv_bfloat16 hi = __float2bfloat16(v);
        const __nv_bfloat16 lo = __float2bfloat16(v - __bfloat162float(hi));
        const int k1 = h, k2 = 64 + h, k3 = 128 + h;
        B2[(k1 >> 4) * (DOUT * 16) + n * 16 + (k1 & 15)] = hi;
        B2[(k2 >> 4) * (DOUT * 16) + n * 16 + (k2 & 15)] = lo;
        B2[(k3 >> 4) * (DOUT * 16) + n * 16 + (k3 & 15)] = hi;
    }
}

// ---------------------------------------------------------------------------
// GEMM1, split-K=2 — unchanged (at mma.sync roofline)
// ---------------------------------------------------------------------------
__global__ void __launch_bounds__(256, 2)
gemm_tc(const __nv_bfloat16* __restrict__ Ag, const __nv_bfloat16* __restrict__ Bg,
        float* __restrict__ Cbase)
{
    extern __shared__ char dynsmem[];

    const int tid  = threadIdx.x;
    const int warp = tid >> 5, lane = tid & 31;
    const int wm = warp >> 2;
    const int wn = warp & 3;
    const int bn = blockIdx.x, bm = blockIdx.y, kz = blockIdx.z;

    const uint32_t abase = (smem_u32(dynsmem) + 1023u) & ~1023u;

    const __nv_bfloat16* Atile = Ag + (long)(bm * 128) * KSPLIT;
    const __nv_bfloat16* Btile = Bg + (long)(bn * 128) * KSPLIT;
    float* C = Cbase + (long)kz * (B_SZ * DOUT);
    const int kbase = kz * (NCHH * KC);

    auto load_chunk = [&](int c, int s) {
        const uint32_t sa = abase + s * STAGEB;
        const uint32_t sb = sa + TILEB;
        const int koff = kbase + c * KC;
        #pragma unroll
        for (int it = 0; it < 4; it++) {
            const int idx = it * 256 + tid;
            const int row = idx >> 3;
            const int c16 = idx & 7;
            const uint32_t soff = swz(row * 128 + c16 * 16);
            cpasync16(sa + soff, Atile + (long)row * KSPLIT + koff + c16 * 8);
            cpasync16(sb + soff, Btile + (long)row * KSPLIT + koff + c16 * 8);
        }
        asm volatile("cp.async.commit_group;" ::: "memory");
    };

    float acc[4][4][4];
    #pragma unroll
    for (int mt = 0; mt < 4; mt++)
        #pragma unroll
        for (int nt = 0; nt < 4; nt++)
            #pragma unroll
            for (int j = 0; j < 4; j++) acc[mt][nt][j] = 0.f;

    const uint32_t a_row = wm * 64 + (lane & 15);
    const uint32_t a_seg = (lane >> 4) * 16;
    const uint32_t b_row4 = wn * 32 + (lane & 7) + ((lane >> 4) << 3);
    const uint32_t b_seg4 = ((lane >> 3) & 1) * 16;

    load_chunk(0, 0);
    load_chunk(1, 1);

    int s_cons = 0, s_load = 2;
    for (int c = 0; c < NCHH; c++) {
        asm volatile("cp.async.wait_group %0;" :: "n"(GS - 2) : "memory");
        __syncthreads();

        const int nl = c + GS - 1;
        if (nl < NCHH) load_chunk(nl, s_load);
        if (++s_load == GS) s_load = 0;

        const uint32_t sa = abase + s_cons * STAGEB;
        const uint32_t sb = sa + TILEB;
        if (++s_cons == GS) s_cons = 0;

        #pragma unroll
        for (int ks = 0; ks < 4; ks++) {
            uint32_t bf[2][4];
            ldsm_x4(bf[0], sb + swz((b_row4)      * 128 + ks * 32 + b_seg4));
            ldsm_x4(bf[1], sb + swz((b_row4 + 16) * 128 + ks * 32 + b_seg4));
            #pragma unroll
            for (int mt = 0; mt < 4; mt++) {
                uint32_t af[4];
                ldsm_x4(af, sa + swz((a_row + mt * 16) * 128 + ks * 32 + a_seg));
                mma16816(acc[mt][0], af, &bf[0][0]);
                mma16816(acc[mt][1], af, &bf[0][2]);
                mma16816(acc[mt][2], af, &bf[1][0]);
                mma16816(acc[mt][3], af, &bf[1][2]);
            }
        }
    }

    const int g  = lane >> 2;
    const int tg = lane & 3;
    #pragma unroll
    for (int mt = 0; mt < 4; mt++) {
        const int m = bm * 128 + wm * 64 + mt * 16 + g;
        #pragma unroll
        for (int nt = 0; nt < 4; nt++) {
            const int n = bn * 128 + wn * 32 + nt * 8 + 2 * tg;
            float2 v0, v1;
            v0.x = acc[mt][nt][0];  v0.y = acc[mt][nt][1];
            v1.x = acc[mt][nt][2];  v1.y = acc[mt][nt][3];
            *(float2*)(C + (long)m * DOUT + n)       = v0;
            *(float2*)(C + (long)(m + 8) * DOUT + n) = v1;
        }
    }
}

// ---------------------------------------------------------------------------
// kan_fused: ROWS=8, 256 thr. Stages load/B/C/D as R12 (measured best).
// Stage E + LayerNorm now on mma.sync: A = [Ghi|Ghi|Glo] (16x192 bf16,
// rows 8-15 zero), B = blocked wo2' streamed in 12 k16 chunks (cp.async,
// 2 buffers aliasing the dead `rows` region).
//
// Dynamic smem layout (bytes):
//   [0, 49152)      : rows[8][512] f32 (first 16384) -> later B chunk bufs (2x24576)
//   [49152, 55552)  : A-tile, 16 rows x 400B pitch (384B data)
//   [55552, 56576)  : Ssh[8][32]
//   [56576, 58624)  : ush[8][64]
//   [58624, 59136)  : red[8][8][2]
//   [59136, 59200)  : muS[8], invS[8]
// ---------------------------------------------------------------------------
#define ROWS 8
#define SM_AT    49152
#define SM_SSH   55552
#define SM_USH   56576
#define SM_RED   58624
#define SM_MU    59136
#define SM_INV   59168
#define KAN_SMEM 59200
#define BCHUNKB  24576          // one B buffer (512 n x 48B pitch)

__global__ void __launch_bounds__(256)
kan_fused(const float* __restrict__ xp0, const float* __restrict__ xp1,
          const float* __restrict__ bp,
          const float* __restrict__ wi1, const float* __restrict__ bi1,
          const float* __restrict__ wi2, const float* __restrict__ bi2,
          const float* __restrict__ wo1, const float* __restrict__ bo1,
          const __nv_bfloat16* __restrict__ B2,
          const float* __restrict__ bo2,
          const float* __restrict__ gamma, const float* __restrict__ beta,
          float* __restrict__ out)
{
    extern __shared__ char sm[];
    float* rows = (float*)sm;                       // [8][512]
    float* Ssh  = (float*)(sm + SM_SSH);            // [8][32]
    float* ush  = (float*)(sm + SM_USH);            // [8][64]
    float* red  = (float*)(sm + SM_RED);            // [8][8][2]
    float* muS  = (float*)(sm + SM_MU);
    float* invS = (float*)(sm + SM_INV);
    const uint32_t smb = smem_u32(sm);

    const int tid  = threadIdx.x;
    const int warp = tid >> 5;
    const int lane = tid & 31;
    const long base = (long)blockIdx.x * ROWS * DOUT;

    // Zero A-tile pad rows 8-15 (384B data region each)
    for (int i = tid; i < 768; i += 256) {
        const int rr = i / 96, c = i % 96;
        *(uint32_t*)(sm + SM_AT + (8 + rr) * 400 + c * 4) = 0u;
    }

    // Load 8 rows: xp0 + xp1 + bias
    {
        const float4* s0 = (const float4*)(xp0 + base);
        const float4* s1 = (const float4*)(xp1 + base);
        const float4* bb = (const float4*)bp;
        float4* dst = (float4*)rows;
        #pragma unroll
        for (int i = 0; i < 4; i++) {
            const int j = tid + i * 256;
            const float4 a = s0[j];
            const float4 b = s1[j];
            const float4 c = bb[j & 127];
            float4 o;
            o.x = a.x + b.x + c.x;
            o.y = a.y + b.y + c.y;
            o.z = a.z + b.z + c.z;
            o.w = a.w + b.w + c.w;
            dst[j] = o;
        }
    }
    __syncthreads();

    // Stage B: S = 0.5*(w*V + 512*b + sum|v*w+b|)  (packed f32x2)
    {
        const float4* rv = (const float4*)(rows + warp * DOUT);

        uint64_t vp = pk2(0.f, 0.f);
        #pragma unroll
        for (int i = 0; i < 4; i++) {
            const float4 v = rv[lane + i * 32];
            vp = add2(vp, pk2(v.x, v.y));
            vp = add2(vp, pk2(v.z, v.w));
        }
        float va, vb; upk2(vp, va, vb);
        float vs = va + vb;
        #pragma unroll
        for (int off = 16; off > 0; off >>= 1)
            vs += __shfl_xor_sync(0xffffffffu, vs, off);

        const float w1 = wi1[lane];
        const float b1 = bi1[lane];
        const uint64_t w11 = pk2(w1, w1);
        const uint64_t b11 = pk2(b1, b1);
        uint64_t s01 = pk2(0.f, 0.f), s23 = pk2(0.f, 0.f);
        #pragma unroll 4
        for (int d4 = 0; d4 < DOUT / 4; d4++) {
            const float4 v = rv[d4];
            s01 = add2(s01, abs2(fma2(pk2(v.x, v.y), w11, b11)));
            s23 = add2(s23, abs2(fma2(pk2(v.z, v.w), w11, b11)));
        }
        float a0, a1, a2, a3;
        upk2(s01, a0, a1); upk2(s23, a2, a3);
        const float sabs = (a0 + a1) + (a2 + a3);
        Ssh[warp * H1_SZ + lane] = 0.5f * (fmaf(w1, vs, (float)DOUT * b1) + sabs);
    }
    __syncthreads();   // rows is dead from here; B-chunk buffers may overwrite it

    // B-chunk loader: chunk kc into buffer s (512 n x 32B, pitch 48B)
    auto load_b2 = [&](int kc, int s) {
        const __nv_bfloat16* src = B2 + (long)kc * (DOUT * 16);
        const uint32_t db = smb + s * BCHUNKB;
        #pragma unroll
        for (int i = 0; i < 4; i++) {
            const int idx = tid + i * 256;      // 0..1023
            const int n = idx >> 1, half = idx & 1;
            cpasync16(db + n * 48 + half * 16, src + n * 16 + half * 8);
        }
        asm volatile("cp.async.commit_group;" ::: "memory");
    };

    // Prefetch first two chunks; they complete during stages C/D.
    load_b2(0, 0);
    load_b2(1, 1);

    // Stage C: u[r][q]
    #pragma unroll
    for (int it = 0; it < 2; it++) {
        const int idx = tid + it * 256;
        const int r = idx >> 6, q = idx & 63;
        float acc = (float)DOUT * bi2[q];
        #pragma unroll
        for (int h = 0; h < H1_SZ; h++)
            acc = fmaf(Ssh[r * H1_SZ + h], wi2[h * Q_SZ + q], acc);
        ush[r * Q_SZ + q] = acc;
    }
    __syncthreads();

    // Stage D: G[r][h2] -> A-tile bf16 hi/lo at row r: k=h2 hi, 64+h2 hi, 128+h2 lo
    #pragma unroll
    for (int it = 0; it < 2; it++) {
        const int idx = tid + it * 256;
        const int r = idx >> 6, h2 = idx & 63;
        const float w = wo1[h2];
        const float b = bo1[h2];
        float g = 0.f;
        #pragma unroll
        for (int q = 0; q < Q_SZ; q++)
            g += fmaxf(fmaf(ush[r * Q_SZ + q], w, b), 0.f);
        const __nv_bfloat16 hi = __float2bfloat16(g);
        const __nv_bfloat16 lo = __float2bfloat16(g - __bfloat162float(hi));
        char* Ar = sm + SM_AT + r * 400;
        *(__nv_bfloat16*)(Ar + 2 * h2)        = hi;
        *(__nv_bfloat16*)(Ar + 128 + 2 * h2)  = hi;
        *(__nv_bfloat16*)(Ar + 256 + 2 * h2)  = lo;
    }
    __syncthreads();

    // Stage E (mma): C[16(8 valid) x 512] = A' @ B'^T over 12 k16 chunks.
    // Warp owns n-slice [warp*64, warp*64+64).
    float c[8][4];
    #pragma unroll
    for (int nt = 0; nt < 8; nt++)
        #pragma unroll
        for (int j = 0; j < 4; j++) c[nt][j] = 0.f;

    const uint32_t a_addr = smb + SM_AT + (lane & 15) * 400 + (lane >> 4) * 16;
    const uint32_t b_lane = (warp * 64 + (lane & 7) + ((lane >> 4) << 3)) * 48
                          + ((lane >> 3) & 1) * 16;

    for (int kc = 0; kc < NKC2; kc++) {
        if (kc == NKC2 - 1)
            asm volatile("cp.async.wait_group 0;" ::: "memory");
        else
            asm volatile("cp.async.wait_group 1;" ::: "memory");
        __syncthreads();

        const uint32_t bb = smb + (kc & 1) * BCHUNKB;
        uint32_t a[4];
        ldsm_x4(a, a_addr + kc * 32);
        uint32_t bf[4][4];
        #pragma unroll
        for (int g2 = 0; g2 < 4; g2++)
            ldsm_x4(bf[g2], bb + b_lane + g2 * (16 * 48));
        #pragma unroll
        for (int nt = 0; nt < 8; nt++)
            mma16816(c[nt], a, &bf[nt >> 1][(nt & 1) * 2]);

        __syncthreads();
        if (kc + 2 < NKC2) load_b2(kc + 2, kc & 1);
    }

    // Epilogue: +Q*bo2, LN stats (valid rows = c[nt][0..1], row g), normalize.
    const int g  = lane >> 2;
    const int tg = lane & 3;

    float ps = 0.f, pq = 0.f;
    #pragma unroll
    for (int nt = 0; nt < 8; nt++) {
        const int n = warp * 64 + nt * 8 + 2 * tg;
        const float2 bo = *(const float2*)(bo2 + n);
        c[nt][0] += (float)Q_SZ * bo.x;
        c[nt][1] += (float)Q_SZ * bo.y;
        ps += c[nt][0] + c[nt][1];
        pq += c[nt][0] * c[nt][0] + c[nt][1] * c[nt][1];
    }
    // reduce over the 4 lanes sharing row g (tg = 0..3)
    ps += __shfl_xor_sync(0xffffffffu, ps, 1);
    pq += __shfl_xor_sync(0xffffffffu, pq, 1);
    ps += __shfl_xor_sync(0xffffffffu, ps, 2);
    pq += __shfl_xor_sync(0xffffffffu, pq, 2);
    if (tg == 0) {
        red[g * 16 + warp * 2 + 0] = ps;
        red[g * 16 + warp * 2 + 1] = pq;
    }
    __syncthreads();

    if (tid < ROWS) {
        float s = 0.f, q2 = 0.f;
        #pragma unroll
        for (int w = 0; w < 8; w++) {
            s  += red[tid * 16 + w * 2 + 0];
            q2 += red[tid * 16 + w * 2 + 1];
        }
        const float mu  = s * (1.f / (float)DOUT);
        const float var = q2 * (1.f / (float)DOUT) - mu * mu;
        muS[tid]  = mu;
        invS[tid] = rsqrtf(var + EPS);
    }
    __syncthreads();

    const float mu  = muS[g];
    const float inv = invS[g];
    #pragma unroll
    for (int nt = 0; nt < 8; nt++) {
        const int n = warp * 64 + nt * 8 + 2 * tg;
        const float2 gm = *(const float2*)(gamma + n);
        const float2 bt = *(const float2*)(beta + n);
        float2 o;
        o.x = (c[nt][0] - mu) * inv * gm.x + bt.x;
        o.y = (c[nt][1] - mu) * inv * gm.y + bt.y;
        *(float2*)(out + base + (long)g * DOUT + n) = o;
    }
}

// ---------------------------------------------------------------------------
// Launch
// ---------------------------------------------------------------------------
extern "C" void kernel_launch(void* const* d_in, const int* in_sizes, int n_in,
                              void* d_out, int out_size)
{
    const float* x     = (const float*)d_in[0];
    const float* wp    = (const float*)d_in[1];
    const float* bp    = (const float*)d_in[2];
    const float* wi1   = (const float*)d_in[3];
    const float* bi1   = (const float*)d_in[4];
    const float* wi2   = (const float*)d_in[5];
    const float* bi2   = (const float*)d_in[6];
    const float* wo1   = (const float*)d_in[7];
    const float* bo1   = (const float*)d_in[8];
    const float* wo2   = (const float*)d_in[9];
    const float* bo2   = (const float*)d_in[10];
    const float* gamma = (const float*)d_in[11];
    const float* beta  = (const float*)d_in[12];
    float* out = (float*)d_out;

    float* xp;             cudaGetSymbolAddress((void**)&xp, g_xp);
    __nv_bfloat16* Ab;     cudaGetSymbolAddress((void**)&Ab, g_A);
    __nv_bfloat16* Bb;     cudaGetSymbolAddress((void**)&Bb, g_Bt);
    __nv_bfloat16* B2b;    cudaGetSymbolAddress((void**)&B2b, g_B2);

    conv_x<<<B_SZ, 256>>>(x, Ab);
    conv_w<<<dim3(DIN / 32, DOUT / 32), 256>>>(wp, Bb);
    conv_wo2<<<DOUT / 256, 256>>>(wo2, B2b);

    const int dyn = GS * STAGEB + 1024;   // ~97 KB
    cudaFuncSetAttribute(gemm_tc, cudaFuncAttributeMaxDynamicSharedMemorySize, dyn);
    gemm_tc<<<dim3(DOUT / 128, B_SZ / 128, 2), 256, dyn>>>(Ab, Bb, xp);

    cudaFuncSetAttribute(kan_fused, cudaFuncAttributeMaxDynamicSharedMemorySize,
                         KAN_SMEM);
    kan_fused<<<B_SZ / ROWS, 256, KAN_SMEM>>>(
        xp, xp + (long)B_SZ * DOUT, bp,
        wi1, bi1, wi2, bi2, wo1, bo1,
        B2b, bo2, gamma, beta, out);
}

// round 14
// speedup vs baseline: 1.8301x; 1.8301x over previous
#include <cuda_runtime.h>
#include <cuda_bf16.h>
#include <cstdint>

// Problem constants
#define B_SZ   4096
#define DIN    768
#define DOUT   512
#define Q_SZ   64
#define H1_SZ  32
#define H2_SZ  64
#define EPS    1e-5f

// GEMM1 split-K: K' = 3 * DIN, A duplicated [hi|hi|lo] (measured best layout)
#define KSPLIT (3 * DIN)          // 2304
#define KC     64
#define NCHH   (KSPLIT / KC / 2)  // 18 chunks per K-half
#define GS     3                  // pipeline stages
#define TILEB  16384              // one 128x64 bf16 tile
#define STAGEB (2 * TILEB)

// ---------------------------------------------------------------------------
// Static device scratch
// ---------------------------------------------------------------------------
__device__ __align__(256) float          g_xp[2][B_SZ * DOUT];          // 16 MB partials
__device__ __align__(256) __nv_bfloat16  g_A[B_SZ * KSPLIT];            // 18.9 MB
__device__ __align__(256) __nv_bfloat16  g_Bt[DOUT * KSPLIT];           // 2.36 MB

// ---------------------------------------------------------------------------
// Helpers
// ---------------------------------------------------------------------------
__device__ __forceinline__ uint32_t smem_u32(const void* p) {
    uint32_t a;
    asm("{ .reg .u64 t; cvta.to.shared.u64 t, %1; cvt.u32.u64 %0, t; }"
        : "=r"(a) : "l"(p));
    return a;
}
__device__ __forceinline__ uint32_t swz(uint32_t off) {
    return off ^ ((off >> 3) & 0x70);
}
__device__ __forceinline__ void cpasync16(uint32_t dst, const void* src) {
    asm volatile("cp.async.cg.shared.global [%0], [%1], 16;"
                 :: "r"(dst), "l"(src) : "memory");
}
__device__ __forceinline__ void ldsm_x4(uint32_t* r, uint32_t addr) {
    asm volatile("ldmatrix.sync.aligned.m8n8.x4.shared.b16 {%0,%1,%2,%3}, [%4];"
                 : "=r"(r[0]), "=r"(r[1]), "=r"(r[2]), "=r"(r[3]) : "r"(addr));
}
__device__ __forceinline__ void mma16816(float* d, const uint32_t* a, const uint32_t* b) {
    asm volatile(
        "mma.sync.aligned.m16n8k16.row.col.f32.bf16.bf16.f32 "
        "{%0,%1,%2,%3}, {%4,%5,%6,%7}, {%8,%9}, {%0,%1,%2,%3};"
        : "+f"(d[0]), "+f"(d[1]), "+f"(d[2]), "+f"(d[3])
        : "r"(a[0]), "r"(a[1]), "r"(a[2]), "r"(a[3]), "r"(b[0]), "r"(b[1]));
}

// ---- packed f32x2 ----
__device__ __forceinline__ uint64_t pk2(float x, float y) {
    uint64_t r; asm("mov.b64 %0,{%1,%2};" : "=l"(r) : "f"(x), "f"(y)); return r;
}
__device__ __forceinline__ void upk2(uint64_t v, float& x, float& y) {
    asm("mov.b64 {%0,%1},%2;" : "=f"(x), "=f"(y) : "l"(v));
}
__device__ __forceinline__ uint64_t fma2(uint64_t a, uint64_t b, uint64_t c) {
    uint64_t d; asm("fma.rn.f32x2 %0,%1,%2,%3;" : "=l"(d) : "l"(a), "l"(b), "l"(c));
    return d;
}
__device__ __forceinline__ uint64_t add2(uint64_t a, uint64_t b) {
    uint64_t d; asm("add.rn.f32x2 %0,%1,%2;" : "=l"(d) : "l"(a), "l"(b));
    return d;
}
__device__ __forceinline__ uint64_t abs2(uint64_t a) {
    uint64_t d; asm("and.b64 %0,%1,0x7FFFFFFF7FFFFFFF;" : "=l"(d) : "l"(a));
    return d;
}

// ---------------------------------------------------------------------------
// Conversions (fp32 -> bf16 hi/lo, 3-term fold into K)
// ---------------------------------------------------------------------------
__global__ void __launch_bounds__(256)
conv_x(const float* __restrict__ x, __nv_bfloat16* __restrict__ A)
{
    const int row = blockIdx.x;
    const float* xr = x + (long)row * DIN;
    __nv_bfloat16* Ar = A + (long)row * KSPLIT;
    #pragma unroll
    for (int i = 0; i < 3; i++) {
        const int k = threadIdx.x + i * 256;
        const float v = xr[k];
        const __nv_bfloat16 hi = __float2bfloat16(v);
        const __nv_bfloat16 lo = __float2bfloat16(v - __bfloat162float(hi));
        Ar[k]            = hi;
        Ar[k + DIN]      = hi;
        Ar[k + 2 * DIN]  = lo;
    }
}

__global__ void __launch_bounds__(256)
conv_w(const float* __restrict__ wp, __nv_bfloat16* __restrict__ Bt)
{
    __shared__ float t[32][33];
    const int k0 = blockIdx.x * 32, n0 = blockIdx.y * 32;
    const int tx = threadIdx.x & 31;
    const int ty = threadIdx.x >> 5;
    #pragma unroll
    for (int dy = 0; dy < 32; dy += 8)
        t[ty + dy][tx] = wp[(long)(k0 + ty + dy) * DOUT + n0 + tx];
    __syncthreads();
    #pragma unroll
    for (int dy = 0; dy < 32; dy += 8) {
        const int n = n0 + ty + dy, k = k0 + tx;
        const float v = t[tx][ty + dy];
        const __nv_bfloat16 hi = __float2bfloat16(v);
        const __nv_bfloat16 lo = __float2bfloat16(v - __bfloat162float(hi));
        __nv_bfloat16* Br = Bt + (long)n * KSPLIT;
        Br[k]           = hi;
        Br[k + DIN]     = lo;
        Br[k + 2 * DIN] = hi;
    }
}

// ---------------------------------------------------------------------------
// GEMM1, split-K=2 — at the mma.sync HMMA roofline (measured 30.8 us best)
// ---------------------------------------------------------------------------
__global__ void __launch_bounds__(256, 2)
gemm_tc(const __nv_bfloat16* __restrict__ Ag, const __nv_bfloat16* __restrict__ Bg,
        float* __restrict__ Cbase)
{
    extern __shared__ char dynsmem[];

    const int tid  = threadIdx.x;
    const int warp = tid >> 5, lane = tid & 31;
    const int wm = warp >> 2;
    const int wn = warp & 3;
    const int bn = blockIdx.x, bm = blockIdx.y, kz = blockIdx.z;

    const uint32_t abase = (smem_u32(dynsmem) + 1023u) & ~1023u;

    const __nv_bfloat16* Atile = Ag + (long)(bm * 128) * KSPLIT;
    const __nv_bfloat16* Btile = Bg + (long)(bn * 128) * KSPLIT;
    float* C = Cbase + (long)kz * (B_SZ * DOUT);
    const int kbase = kz * (NCHH * KC);

    auto load_chunk = [&](int c, int s) {
        const uint32_t sa = abase + s * STAGEB;
        const uint32_t sb = sa + TILEB;
        const int koff = kbase + c * KC;
        #pragma unroll
        for (int it = 0; it < 4; it++) {
            const int idx = it * 256 + tid;
            const int row = idx >> 3;
            const int c16 = idx & 7;
            const uint32_t soff = swz(row * 128 + c16 * 16);
            cpasync16(sa + soff, Atile + (long)row * KSPLIT + koff + c16 * 8);
            cpasync16(sb + soff, Btile + (long)row * KSPLIT + koff + c16 * 8);
        }
        asm volatile("cp.async.commit_group;" ::: "memory");
    };

    float acc[4][4][4];
    #pragma unroll
    for (int mt = 0; mt < 4; mt++)
        #pragma unroll
        for (int nt = 0; nt < 4; nt++)
            #pragma unroll
            for (int j = 0; j < 4; j++) acc[mt][nt][j] = 0.f;

    const uint32_t a_row = wm * 64 + (lane & 15);
    const uint32_t a_seg = (lane >> 4) * 16;
    const uint32_t b_row4 = wn * 32 + (lane & 7) + ((lane >> 4) << 3);
    const uint32_t b_seg4 = ((lane >> 3) & 1) * 16;

    load_chunk(0, 0);
    load_chunk(1, 1);

    int s_cons = 0, s_load = 2;
    for (int c = 0; c < NCHH; c++) {
        asm volatile("cp.async.wait_group %0;" :: "n"(GS - 2) : "memory");
        __syncthreads();

        const int nl = c + GS - 1;
        if (nl < NCHH) load_chunk(nl, s_load);
        if (++s_load == GS) s_load = 0;

        const uint32_t sa = abase + s_cons * STAGEB;
        const uint32_t sb = sa + TILEB;
        if (++s_cons == GS) s_cons = 0;

        #pragma unroll
        for (int ks = 0; ks < 4; ks++) {
            uint32_t bf[2][4];
            ldsm_x4(bf[0], sb + swz((b_row4)      * 128 + ks * 32 + b_seg4));
            ldsm_x4(bf[1], sb + swz((b_row4 + 16) * 128 + ks * 32 + b_seg4));
            #pragma unroll
            for (int mt = 0; mt < 4; mt++) {
                uint32_t af[4];
                ldsm_x4(af, sa + swz((a_row + mt * 16) * 128 + ks * 32 + a_seg));
                mma16816(acc[mt][0], af, &bf[0][0]);
                mma16816(acc[mt][1], af, &bf[0][2]);
                mma16816(acc[mt][2], af, &bf[1][0]);
                mma16816(acc[mt][3], af, &bf[1][2]);
            }
        }
    }

    const int g  = lane >> 2;
    const int tg = lane & 3;
    #pragma unroll
    for (int mt = 0; mt < 4; mt++) {
        const int m = bm * 128 + wm * 64 + mt * 16 + g;
        #pragma unroll
        for (int nt = 0; nt < 4; nt++) {
            const int n = bn * 128 + wn * 32 + nt * 8 + 2 * tg;
            float2 v0, v1;
            v0.x = acc[mt][nt][0];  v0.y = acc[mt][nt][1];
            v1.x = acc[mt][nt][2];  v1.y = acc[mt][nt][3];
            *(float2*)(C + (long)m * DOUT + n)       = v0;
            *(float2*)(C + (long)(m + 8) * DOUT + n) = v1;
        }
    }
}

// ---------------------------------------------------------------------------
// Kernel 2: scalar pipeline, R7 structure (measured best 27.1-27.5 us across
// three runs): ROWS=8, 256 threads, abs-identity + packed f32x2, GshT.
// ---------------------------------------------------------------------------
#define ROWS 8

__global__ void __launch_bounds__(256)
kan_fused(const float* __restrict__ xp0, const float* __restrict__ xp1,
          const float* __restrict__ bp,
          const float* __restrict__ wi1, const float* __restrict__ bi1,
          const float* __restrict__ wi2, const float* __restrict__ bi2,
          const float* __restrict__ wo1, const float* __restrict__ bo1,
          const float* __restrict__ wo2, const float* __restrict__ bo2,
          const float* __restrict__ gamma, const float* __restrict__ beta,
          float* __restrict__ out)
{
    __shared__ float rows[ROWS][DOUT];
    __shared__ float Ssh[ROWS][H1_SZ];
    __shared__ float ush[ROWS][Q_SZ];
    __shared__ float GshT[H2_SZ][ROWS];     // transposed: [h2][r]
    __shared__ float red[ROWS][8][2];

    const int tid  = threadIdx.x;
    const int warp = tid >> 5;
    const int lane = tid & 31;
    const long base = (long)blockIdx.x * ROWS * DOUT;

    // Load 8 rows: xp0 + xp1 + bias
    {
        const float4* s0 = (const float4*)(xp0 + base);
        const float4* s1 = (const float4*)(xp1 + base);
        const float4* bb = (const float4*)bp;
        float4* dst = (float4*)(&rows[0][0]);
        #pragma unroll
        for (int i = 0; i < 4; i++) {
            const int j = tid + i * 256;
            const float4 a = s0[j];
            const float4 b = s1[j];
            const float4 c = bb[j & 127];
            float4 o;
            o.x = a.x + b.x + c.x;
            o.y = a.y + b.y + c.y;
            o.z = a.z + b.z + c.z;
            o.w = a.w + b.w + c.w;
            dst[j] = o;
        }
    }
    __syncthreads();

    // Stage B: S = 0.5*(w*V + 512*b + sum|v*w+b|)   (packed f32x2)
    {
        const float4* rv = (const float4*)(&rows[warp][0]);

        uint64_t vp = pk2(0.f, 0.f);
        #pragma unroll
        for (int i = 0; i < 4; i++) {
            const float4 v = rv[lane + i * 32];
            vp = add2(vp, pk2(v.x, v.y));
            vp = add2(vp, pk2(v.z, v.w));
        }
        float va, vb; upk2(vp, va, vb);
        float vs = va + vb;
        #pragma unroll
        for (int off = 16; off > 0; off >>= 1)
            vs += __shfl_xor_sync(0xffffffffu, vs, off);

        const float w1 = wi1[lane];
        const float b1 = bi1[lane];
        const uint64_t w11 = pk2(w1, w1);
        const uint64_t b11 = pk2(b1, b1);
        uint64_t s01 = pk2(0.f, 0.f), s23 = pk2(0.f, 0.f);
        #pragma unroll 4
        for (int d4 = 0; d4 < DOUT / 4; d4++) {
            const float4 v = rv[d4];
            s01 = add2(s01, abs2(fma2(pk2(v.x, v.y), w11, b11)));
            s23 = add2(s23, abs2(fma2(pk2(v.z, v.w), w11, b11)));
        }
        float a0, a1, a2, a3;
        upk2(s01, a0, a1); upk2(s23, a2, a3);
        const float sabs = (a0 + a1) + (a2 + a3);
        Ssh[warp][lane] = 0.5f * (fmaf(w1, vs, (float)DOUT * b1) + sabs);
    }
    __syncthreads();

    // Stage C: u[r][q]
    #pragma unroll
    for (int it = 0; it < 2; it++) {
        const int idx = tid + it * 256;
        const int r = idx >> 6, q = idx & 63;
        float acc = (float)DOUT * bi2[q];
        #pragma unroll
        for (int h = 0; h < H1_SZ; h++)
            acc = fmaf(Ssh[r][h], wi2[h * Q_SZ + q], acc);
        ush[r][q] = acc;
    }
    __syncthreads();

    // Stage D: G[r][h2] -> stored transposed
    #pragma unroll
    for (int it = 0; it < 2; it++) {
        const int idx = tid + it * 256;
        const int r = idx >> 6, h2 = idx & 63;
        const float w = wo1[h2];
        const float b = bo1[h2];
        float g = 0.f;
        #pragma unroll
        for (int q = 0; q < Q_SZ; q++)
            g += fmaxf(fmaf(ush[r][q], w, b), 0.f);
        GshT[h2][r] = g;
    }
    __syncthreads();

    // Stage E (packed f32x2): rows packed in pairs from float4 broadcasts.
    const int d0 = tid * 2;
    uint64_t acc2[8];
    #pragma unroll
    for (int j = 0; j < 8; j++) acc2[j] = pk2(0.f, 0.f);

    #pragma unroll 4
    for (int h2 = 0; h2 < H2_SZ; h2++) {
        const float2 w = *(const float2*)(wo2 + h2 * DOUT + d0);   // LDG.64
        const uint64_t wx = pk2(w.x, w.x);
        const uint64_t wy = pk2(w.y, w.y);
        const float4 ga = *(const float4*)(&GshT[h2][0]);          // rows 0-3 bcast
        const float4 gb = *(const float4*)(&GshT[h2][4]);          // rows 4-7 bcast
        const uint64_t g01 = pk2(ga.x, ga.y);
        const uint64_t g23 = pk2(ga.z, ga.w);
        const uint64_t g45 = pk2(gb.x, gb.y);
        const uint64_t g67 = pk2(gb.z, gb.w);
        acc2[0] = fma2(g01, wx, acc2[0]);
        acc2[1] = fma2(g23, wx, acc2[1]);
        acc2[2] = fma2(g45, wx, acc2[2]);
        acc2[3] = fma2(g67, wx, acc2[3]);
        acc2[4] = fma2(g01, wy, acc2[4]);
        acc2[5] = fma2(g23, wy, acc2[5]);
        acc2[6] = fma2(g45, wy, acc2[6]);
        acc2[7] = fma2(g67, wy, acc2[7]);
    }

    float ax[ROWS], ay[ROWS];
    {
        const float2 bo = *(const float2*)(bo2 + d0);
        const uint64_t bbx = pk2((float)Q_SZ * bo.x, (float)Q_SZ * bo.x);
        const uint64_t bby = pk2((float)Q_SZ * bo.y, (float)Q_SZ * bo.y);
        #pragma unroll
        for (int p = 0; p < 4; p++) {
            acc2[p]     = add2(acc2[p], bbx);
            acc2[4 + p] = add2(acc2[4 + p], bby);
            upk2(acc2[p],     ax[2 * p], ax[2 * p + 1]);
            upk2(acc2[4 + p], ay[2 * p], ay[2 * p + 1]);
        }
    }

    // LayerNorm reductions
    #pragma unroll
    for (int r = 0; r < ROWS; r++) {
        float ps = ax[r] + ay[r];
        float pq = ax[r] * ax[r] + ay[r] * ay[r];
        #pragma unroll
        for (int off = 16; off > 0; off >>= 1) {
            ps += __shfl_xor_sync(0xffffffffu, ps, off);
            pq += __shfl_xor_sync(0xffffffffu, pq, off);
        }
        if (lane == 0) { red[r][warp][0] = ps; red[r][warp][1] = pq; }
    }
    __syncthreads();

    const float2 gm = *(const float2*)(gamma + d0);
    const float2 bt = *(const float2*)(beta + d0);
    #pragma unroll
    for (int r = 0; r < ROWS; r++) {
        float s = 0.f, q2 = 0.f;
        #pragma unroll
        for (int w = 0; w < 8; w++) { s += red[r][w][0]; q2 += red[r][w][1]; }
        const float mu  = s * (1.f / (float)DOUT);
        const float var = q2 * (1.f / (float)DOUT) - mu * mu;
        const float inv = rsqrtf(var + EPS);
        float2 o;
        o.x = (ax[r] - mu) * inv * gm.x + bt.x;
        o.y = (ay[r] - mu) * inv * gm.y + bt.y;
        *(float2*)(out + base + (long)r * DOUT + d0) = o;
    }
}

// ---------------------------------------------------------------------------
// Launch
// ---------------------------------------------------------------------------
extern "C" void kernel_launch(void* const* d_in, const int* in_sizes, int n_in,
                              void* d_out, int out_size)
{
    const float* x     = (const float*)d_in[0];
    const float* wp    = (const float*)d_in[1];
    const float* bp    = (const float*)d_in[2];
    const float* wi1   = (const float*)d_in[3];
    const float* bi1   = (const float*)d_in[4];
    const float* wi2   = (const float*)d_in[5];
    const float* bi2   = (const float*)d_in[6];
    const float* wo1   = (const float*)d_in[7];
    const float* bo1   = (const float*)d_in[8];
    const float* wo2   = (const float*)d_in[9];
    const float* bo2   = (const float*)d_in[10];
    const float* gamma = (const float*)d_in[11];
    const float* beta  = (const float*)d_in[12];
    float* out = (float*)d_out;

    float* xp;             cudaGetSymbolAddress((void**)&xp, g_xp);
    __nv_bfloat16* Ab;     cudaGetSymbolAddress((void**)&Ab, g_A);
    __nv_bfloat16* Bb;     cudaGetSymbolAddress((void**)&Bb, g_Bt);

    conv_x<<<B_SZ, 256>>>(x, Ab);
    conv_w<<<dim3(DIN / 32, DOUT / 32), 256>>>(wp, Bb);

    const int dyn = GS * STAGEB + 1024;   // ~97 KB
    cudaFuncSetAttribute(gemm_tc, cudaFuncAttributeMaxDynamicSharedMemorySize, dyn);
    gemm_tc<<<dim3(DOUT / 128, B_SZ / 128, 2), 256, dyn>>>(Ab, Bb, xp);

    kan_fused<<<B_SZ / ROWS, 256>>>(xp, xp + (long)B_SZ * DOUT, bp,
                                    wi1, bi1, wi2, bi2,
                                    wo1, bo1, wo2, bo2, gamma, beta, out);
}

// round 15
// speedup vs baseline: 1.8926x; 1.0342x over previous
#include <cuda_runtime.h>
#include <cuda_bf16.h>
#include <cstdint>

// Problem constants
#define B_SZ   4096
#define DIN    768
#define DOUT   512
#define Q_SZ   64
#define H1_SZ  32
#define H2_SZ  64
#define EPS    1e-5f

// GEMM1 split-K: K' = 3 * DIN, A duplicated [hi|hi|lo]
#define KSPLIT (3 * DIN)          // 2304
#define KC     64
#define NCHH   (KSPLIT / KC / 2)  // 18 chunks per K-half
#define GS     3                  // pipeline stages
#define TILEB  16384              // one 128x64 bf16 tile
#define STAGEB (2 * TILEB)

// merged conv grid split
#define CVX_BLOCKS 512            // conv_x part: 8 rows/block
#define CVW_BLOCKS ((DIN / 32) * (DOUT / 32))   // 24*16 = 384

// ---------------------------------------------------------------------------
// Static device scratch
// ---------------------------------------------------------------------------
__device__ __align__(256) float          g_xp[2][B_SZ * DOUT];          // 16 MB partials
__device__ __align__(256) __nv_bfloat16  g_A[B_SZ * KSPLIT];            // 18.9 MB
__device__ __align__(256) __nv_bfloat16  g_Bt[DOUT * KSPLIT];           // 2.36 MB

// ---------------------------------------------------------------------------
// Helpers
// ---------------------------------------------------------------------------
__device__ __forceinline__ uint32_t smem_u32(const void* p) {
    uint32_t a;
    asm("{ .reg .u64 t; cvta.to.shared.u64 t, %1; cvt.u32.u64 %0, t; }"
        : "=r"(a) : "l"(p));
    return a;
}
__device__ __forceinline__ uint32_t swz(uint32_t off) {
    return off ^ ((off >> 3) & 0x70);
}
__device__ __forceinline__ void cpasync16(uint32_t dst, const void* src) {
    asm volatile("cp.async.cg.shared.global [%0], [%1], 16;"
                 :: "r"(dst), "l"(src) : "memory");
}
__device__ __forceinline__ void ldsm_x4(uint32_t* r, uint32_t addr) {
    asm volatile("ldmatrix.sync.aligned.m8n8.x4.shared.b16 {%0,%1,%2,%3}, [%4];"
                 : "=r"(r[0]), "=r"(r[1]), "=r"(r[2]), "=r"(r[3]) : "r"(addr));
}
__device__ __forceinline__ void mma16816(float* d, const uint32_t* a, const uint32_t* b) {
    asm volatile(
        "mma.sync.aligned.m16n8k16.row.col.f32.bf16.bf16.f32 "
        "{%0,%1,%2,%3}, {%4,%5,%6,%7}, {%8,%9}, {%0,%1,%2,%3};"
        : "+f"(d[0]), "+f"(d[1]), "+f"(d[2]), "+f"(d[3])
        : "r"(a[0]), "r"(a[1]), "r"(a[2]), "r"(a[3]), "r"(b[0]), "r"(b[1]));
}

// ---- packed f32x2 ----
__device__ __forceinline__ uint64_t pk2(float x, float y) {
    uint64_t r; asm("mov.b64 %0,{%1,%2};" : "=l"(r) : "f"(x), "f"(y)); return r;
}
__device__ __forceinline__ void upk2(uint64_t v, float& x, float& y) {
    asm("mov.b64 {%0,%1},%2;" : "=f"(x), "=f"(y) : "l"(v));
}
__device__ __forceinline__ uint64_t fma2(uint64_t a, uint64_t b, uint64_t c) {
    uint64_t d; asm("fma.rn.f32x2 %0,%1,%2,%3;" : "=l"(d) : "l"(a), "l"(b), "l"(c));
    return d;
}
__device__ __forceinline__ uint64_t add2(uint64_t a, uint64_t b) {
    uint64_t d; asm("add.rn.f32x2 %0,%1,%2;" : "=l"(d) : "l"(a), "l"(b));
    return d;
}
__device__ __forceinline__ uint64_t abs2(uint64_t a) {
    uint64_t d; asm("and.b64 %0,%1,0x7FFFFFFF7FFFFFFF;" : "=l"(d) : "l"(a));
    return d;
}

// pack two bf16(hi-of-float) into one uint32
__device__ __forceinline__ uint32_t pack_bf2(__nv_bfloat16 a, __nv_bfloat16 b) {
    __nv_bfloat162 t;
    t.x = a; t.y = b;
    return *(uint32_t*)&t;
}

// ---------------------------------------------------------------------------
// Merged conversion kernel.
// Blocks [0, CVX_BLOCKS):   x -> A = [hi | hi | lo], vectorized (STG.128).
// Blocks [CVX_BLOCKS, ...): wp -> Bt = [hi ; lo ; hi] per n-row.
// ---------------------------------------------------------------------------
__global__ void __launch_bounds__(256)
conv_all(const float* __restrict__ x, __nv_bfloat16* __restrict__ A,
         const float* __restrict__ wp, __nv_bfloat16* __restrict__ Bt)
{
    if (blockIdx.x < CVX_BLOCKS) {
        // conv_x: 8 rows per block; 768 groups of 8 elems; 3 groups/thread
        const int r0 = blockIdx.x * 8;
        #pragma unroll
        for (int it = 0; it < 3; it++) {
            const int g = threadIdx.x + it * 256;     // 0..767
            const int row = r0 + (g / 96);
            const int k0  = (g % 96) * 8;
            const float4* xr = (const float4*)(x + (long)row * DIN + k0);
            const float4 va = xr[0];
            const float4 vb = xr[1];
            const float vv[8] = {va.x, va.y, va.z, va.w, vb.x, vb.y, vb.z, vb.w};
            uint32_t h[4], l[4];
            #pragma unroll
            for (int j = 0; j < 4; j++) {
                const float a = vv[2 * j], b = vv[2 * j + 1];
                const __nv_bfloat16 ha = __float2bfloat16(a);
                const __nv_bfloat16 hb = __float2bfloat16(b);
                h[j] = pack_bf2(ha, hb);
                l[j] = pack_bf2(__float2bfloat16(a - __bfloat162float(ha)),
                                __float2bfloat16(b - __bfloat162float(hb)));
            }
            __nv_bfloat16* Ar = A + (long)row * KSPLIT + k0;
            *(uint4*)(Ar)           = *(uint4*)h;
            *(uint4*)(Ar + DIN)     = *(uint4*)h;
            *(uint4*)(Ar + 2 * DIN) = *(uint4*)l;
        }
    } else {
        // conv_w: 32x32 transpose tile
        __shared__ float t[32][33];
        const int bid = blockIdx.x - CVX_BLOCKS;
        const int k0 = (bid % (DIN / 32)) * 32;
        const int n0 = (bid / (DIN / 32)) * 32;
        const int tx = threadIdx.x & 31;
        const int ty = threadIdx.x >> 5;
        #pragma unroll
        for (int dy = 0; dy < 32; dy += 8)
            t[ty + dy][tx] = wp[(long)(k0 + ty + dy) * DOUT + n0 + tx];
        __syncthreads();
        #pragma unroll
        for (int dy = 0; dy < 32; dy += 8) {
            const int n = n0 + ty + dy, k = k0 + tx;
            const float v = t[tx][ty + dy];
            const __nv_bfloat16 hi = __float2bfloat16(v);
            const __nv_bfloat16 lo = __float2bfloat16(v - __bfloat162float(hi));
            __nv_bfloat16* Br = Bt + (long)n * KSPLIT;
            Br[k]           = hi;
            Br[k + DIN]     = lo;
            Br[k + 2 * DIN] = hi;
        }
    }
}

// ---------------------------------------------------------------------------
// GEMM1, split-K=2 — unchanged (measured best)
// ---------------------------------------------------------------------------
__global__ void __launch_bounds__(256, 2)
gemm_tc(const __nv_bfloat16* __restrict__ Ag, const __nv_bfloat16* __restrict__ Bg,
        float* __restrict__ Cbase)
{
    extern __shared__ char dynsmem[];

    const int tid  = threadIdx.x;
    const int warp = tid >> 5, lane = tid & 31;
    const int wm = warp >> 2;
    const int wn = warp & 3;
    const int bn = blockIdx.x, bm = blockIdx.y, kz = blockIdx.z;

    const uint32_t abase = (smem_u32(dynsmem) + 1023u) & ~1023u;

    const __nv_bfloat16* Atile = Ag + (long)(bm * 128) * KSPLIT;
    const __nv_bfloat16* Btile = Bg + (long)(bn * 128) * KSPLIT;
    float* C = Cbase + (long)kz * (B_SZ * DOUT);
    const int kbase = kz * (NCHH * KC);

    auto load_chunk = [&](int c, int s) {
        const uint32_t sa = abase + s * STAGEB;
        const uint32_t sb = sa + TILEB;
        const int koff = kbase + c * KC;
        #pragma unroll
        for (int it = 0; it < 4; it++) {
            const int idx = it * 256 + tid;
            const int row = idx >> 3;
            const int c16 = idx & 7;
            const uint32_t soff = swz(row * 128 + c16 * 16);
            cpasync16(sa + soff, Atile + (long)row * KSPLIT + koff + c16 * 8);
            cpasync16(sb + soff, Btile + (long)row * KSPLIT + koff + c16 * 8);
        }
        asm volatile("cp.async.commit_group;" ::: "memory");
    };

    float acc[4][4][4];
    #pragma unroll
    for (int mt = 0; mt < 4; mt++)
        #pragma unroll
        for (int nt = 0; nt < 4; nt++)
            #pragma unroll
            for (int j = 0; j < 4; j++) acc[mt][nt][j] = 0.f;

    const uint32_t a_row = wm * 64 + (lane & 15);
    const uint32_t a_seg = (lane >> 4) * 16;
    const uint32_t b_row4 = wn * 32 + (lane & 7) + ((lane >> 4) << 3);
    const uint32_t b_seg4 = ((lane >> 3) & 1) * 16;

    load_chunk(0, 0);
    load_chunk(1, 1);

    int s_cons = 0, s_load = 2;
    for (int c = 0; c < NCHH; c++) {
        asm volatile("cp.async.wait_group %0;" :: "n"(GS - 2) : "memory");
        __syncthreads();

        const int nl = c + GS - 1;
        if (nl < NCHH) load_chunk(nl, s_load);
        if (++s_load == GS) s_load = 0;

        const uint32_t sa = abase + s_cons * STAGEB;
        const uint32_t sb = sa + TILEB;
        if (++s_cons == GS) s_cons = 0;

        #pragma unroll
        for (int ks = 0; ks < 4; ks++) {
            uint32_t bf[2][4];
            ldsm_x4(bf[0], sb + swz((b_row4)      * 128 + ks * 32 + b_seg4));
            ldsm_x4(bf[1], sb + swz((b_row4 + 16) * 128 + ks * 32 + b_seg4));
            #pragma unroll
            for (int mt = 0; mt < 4; mt++) {
                uint32_t af[4];
                ldsm_x4(af, sa + swz((a_row + mt * 16) * 128 + ks * 32 + a_seg));
                mma16816(acc[mt][0], af, &bf[0][0]);
                mma16816(acc[mt][1], af, &bf[0][2]);
                mma16816(acc[mt][2], af, &bf[1][0]);
                mma16816(acc[mt][3], af, &bf[1][2]);
            }
        }
    }

    const int g  = lane >> 2;
    const int tg = lane & 3;
    #pragma unroll
    for (int mt = 0; mt < 4; mt++) {
        const int m = bm * 128 + wm * 64 + mt * 16 + g;
        #pragma unroll
        for (int nt = 0; nt < 4; nt++) {
            const int n = bn * 128 + wn * 32 + nt * 8 + 2 * tg;
            float2 v0, v1;
            v0.x = acc[mt][nt][0];  v0.y = acc[mt][nt][1];
            v1.x = acc[mt][nt][2];  v1.y = acc[mt][nt][3];
            *(float2*)(C + (long)m * DOUT + n)       = v0;
            *(float2*)(C + (long)(m + 8) * DOUT + n) = v1;
        }
    }
}

// ---------------------------------------------------------------------------
// Kernel 2: scalar pipeline, R7 structure — unchanged (measured best 26.9 us)
// ---------------------------------------------------------------------------
#define ROWS 8

__global__ void __launch_bounds__(256)
kan_fused(const float* __restrict__ xp0, const float* __restrict__ xp1,
          const float* __restrict__ bp,
          const float* __restrict__ wi1, const float* __restrict__ bi1,
          const float* __restrict__ wi2, const float* __restrict__ bi2,
          const float* __restrict__ wo1, const float* __restrict__ bo1,
          const float* __restrict__ wo2, const float* __restrict__ bo2,
          const float* __restrict__ gamma, const float* __restrict__ beta,
          float* __restrict__ out)
{
    __shared__ float rows[ROWS][DOUT];
    __shared__ float Ssh[ROWS][H1_SZ];
    __shared__ float ush[ROWS][Q_SZ];
    __shared__ float GshT[H2_SZ][ROWS];     // transposed: [h2][r]
    __shared__ float red[ROWS][8][2];

    const int tid  = threadIdx.x;
    const int warp = tid >> 5;
    const int lane = tid & 31;
    const long base = (long)blockIdx.x * ROWS * DOUT;

    // Load 8 rows: xp0 + xp1 + bias
    {
        const float4* s0 = (const float4*)(xp0 + base);
        const float4* s1 = (const float4*)(xp1 + base);
        const float4* bb = (const float4*)bp;
        float4* dst = (float4*)(&rows[0][0]);
        #pragma unroll
        for (int i = 0; i < 4; i++) {
            const int j = tid + i * 256;
            const float4 a = s0[j];
            const float4 b = s1[j];
            const float4 c = bb[j & 127];
            float4 o;
            o.x = a.x + b.x + c.x;
            o.y = a.y + b.y + c.y;
            o.z = a.z + b.z + c.z;
            o.w = a.w + b.w + c.w;
            dst[j] = o;
        }
    }
    __syncthreads();

    // Stage B: S = 0.5*(w*V + 512*b + sum|v*w+b|)   (packed f32x2)
    {
        const float4* rv = (const float4*)(&rows[warp][0]);

        uint64_t vp = pk2(0.f, 0.f);
        #pragma unroll
        for (int i = 0; i < 4; i++) {
            const float4 v = rv[lane + i * 32];
            vp = add2(vp, pk2(v.x, v.y));
            vp = add2(vp, pk2(v.z, v.w));
        }
        float va, vb; upk2(vp, va, vb);
        float vs = va + vb;
        #pragma unroll
        for (int off = 16; off > 0; off >>= 1)
            vs += __shfl_xor_sync(0xffffffffu, vs, off);

        const float w1 = wi1[lane];
        const float b1 = bi1[lane];
        const uint64_t w11 = pk2(w1, w1);
        const uint64_t b11 = pk2(b1, b1);
        uint64_t s01 = pk2(0.f, 0.f), s23 = pk2(0.f, 0.f);
        #pragma unroll 4
        for (int d4 = 0; d4 < DOUT / 4; d4++) {
            const float4 v = rv[d4];
            s01 = add2(s01, abs2(fma2(pk2(v.x, v.y), w11, b11)));
            s23 = add2(s23, abs2(fma2(pk2(v.z, v.w), w11, b11)));
        }
        float a0, a1, a2, a3;
        upk2(s01, a0, a1); upk2(s23, a2, a3);
        const float sabs = (a0 + a1) + (a2 + a3);
        Ssh[warp][lane] = 0.5f * (fmaf(w1, vs, (float)DOUT * b1) + sabs);
    }
    __syncthreads();

    // Stage C: u[r][q]
    #pragma unroll
    for (int it = 0; it < 2; it++) {
        const int idx = tid + it * 256;
        const int r = idx >> 6, q = idx & 63;
        float acc = (float)DOUT * bi2[q];
        #pragma unroll
        for (int h = 0; h < H1_SZ; h++)
            acc = fmaf(Ssh[r][h], wi2[h * Q_SZ + q], acc);
        ush[r][q] = acc;
    }
    __syncthreads();

    // Stage D: G[r][h2] -> stored transposed
    #pragma unroll
    for (int it = 0; it < 2; it++) {
        const int idx = tid + it * 256;
        const int r = idx >> 6, h2 = idx & 63;
        const float w = wo1[h2];
        const float b = bo1[h2];
        float g = 0.f;
        #pragma unroll
        for (int q = 0; q < Q_SZ; q++)
            g += fmaxf(fmaf(ush[r][q], w, b), 0.f);
        GshT[h2][r] = g;
    }
    __syncthreads();

    // Stage E (packed f32x2): rows packed in pairs from float4 broadcasts.
    const int d0 = tid * 2;
    uint64_t acc2[8];
    #pragma unroll
    for (int j = 0; j < 8; j++) acc2[j] = pk2(0.f, 0.f);

    #pragma unroll 4
    for (int h2 = 0; h2 < H2_SZ; h2++) {
        const float2 w = *(const float2*)(wo2 + h2 * DOUT + d0);   // LDG.64
        const uint64_t wx = pk2(w.x, w.x);
        const uint64_t wy = pk2(w.y, w.y);
        const float4 ga = *(const float4*)(&GshT[h2][0]);          // rows 0-3 bcast
        const float4 gb = *(const float4*)(&GshT[h2][4]);          // rows 4-7 bcast
        const uint64_t g01 = pk2(ga.x, ga.y);
        const uint64_t g23 = pk2(ga.z, ga.w);
        const uint64_t g45 = pk2(gb.x, gb.y);
        const uint64_t g67 = pk2(gb.z, gb.w);
        acc2[0] = fma2(g01, wx, acc2[0]);
        acc2[1] = fma2(g23, wx, acc2[1]);
        acc2[2] = fma2(g45, wx, acc2[2]);
        acc2[3] = fma2(g67, wx, acc2[3]);
        acc2[4] = fma2(g01, wy, acc2[4]);
        acc2[5] = fma2(g23, wy, acc2[5]);
        acc2[6] = fma2(g45, wy, acc2[6]);
        acc2[7] = fma2(g67, wy, acc2[7]);
    }

    float ax[ROWS], ay[ROWS];
    {
        const float2 bo = *(const float2*)(bo2 + d0);
        const uint64_t bbx = pk2((float)Q_SZ * bo.x, (float)Q_SZ * bo.x);
        const uint64_t bby = pk2((float)Q_SZ * bo.y, (float)Q_SZ * bo.y);
        #pragma unroll
        for (int p = 0; p < 4; p++) {
            acc2[p]     = add2(acc2[p], bbx);
            acc2[4 + p] = add2(acc2[4 + p], bby);
            upk2(acc2[p],     ax[2 * p], ax[2 * p + 1]);
            upk2(acc2[4 + p], ay[2 * p], ay[2 * p + 1]);
        }
    }

    // LayerNorm reductions
    #pragma unroll
    for (int r = 0; r < ROWS; r++) {
        float ps = ax[r] + ay[r];
        float pq = ax[r] * ax[r] + ay[r] * ay[r];
        #pragma unroll
        for (int off = 16; off > 0; off >>= 1) {
            ps += __shfl_xor_sync(0xffffffffu, ps, off);
            pq += __shfl_xor_sync(0xffffffffu, pq, off);
        }
        if (lane == 0) { red[r][warp][0] = ps; red[r][warp][1] = pq; }
    }
    __syncthreads();

    const float2 gm = *(const float2*)(gamma + d0);
    const float2 bt = *(const float2*)(beta + d0);
    #pragma unroll
    for (int r = 0; r < ROWS; r++) {
        float s = 0.f, q2 = 0.f;
        #pragma unroll
        for (int w = 0; w < 8; w++) { s += red[r][w][0]; q2 += red[r][w][1]; }
        const float mu  = s * (1.f / (float)DOUT);
        const float var = q2 * (1.f / (float)DOUT) - mu * mu;
        const float inv = rsqrtf(var + EPS);
        float2 o;
        o.x = (ax[r] - mu) * inv * gm.x + bt.x;
        o.y = (ay[r] - mu) * inv * gm.y + bt.y;
        *(float2*)(out + base + (long)r * DOUT + d0) = o;
    }
}

// ---------------------------------------------------------------------------
// Launch
// ---------------------------------------------------------------------------
extern "C" void kernel_launch(void* const* d_in, const int* in_sizes, int n_in,
                              void* d_out, int out_size)
{
    const float* x     = (const float*)d_in[0];
    const float* wp    = (const float*)d_in[1];
    const float* bp    = (const float*)d_in[2];
    const float* wi1   = (const float*)d_in[3];
    const float* bi1   = (const float*)d_in[4];
    const float* wi2   = (const float*)d_in[5];
    const float* bi2   = (const float*)d_in[6];
    const float* wo1   = (const float*)d_in[7];
    const float* bo1   = (const float*)d_in[8];
    const float* wo2   = (const float*)d_in[9];
    const float* bo2   = (const float*)d_in[10];
    const float* gamma = (const float*)d_in[11];
    const float* beta  = (const float*)d_in[12];
    float* out = (float*)d_out;

    float* xp;             cudaGetSymbolAddress((void**)&xp, g_xp);
    __nv_bfloat16* Ab;     cudaGetSymbolAddress((void**)&Ab, g_A);
    __nv_bfloat16* Bb;     cudaGetSymbolAddress((void**)&Bb, g_Bt);

    conv_all<<<CVX_BLOCKS + CVW_BLOCKS, 256>>>(x, Ab, wp, Bb);

    const int dyn = GS * STAGEB + 1024;   // ~97 KB
    cudaFuncSetAttribute(gemm_tc, cudaFuncAttributeMaxDynamicSharedMemorySize, dyn);
    gemm_tc<<<dim3(DOUT / 128, B_SZ / 128, 2), 256, dyn>>>(Ab, Bb, xp);

    kan_fused<<<B_SZ / ROWS, 256>>>(xp, xp + (long)B_SZ * DOUT, bp,
                                    wi1, bi1, wi2, bi2,
                                    wo1, bo1, wo2, bo2, gamma, beta, out);
}

// round 16
// speedup vs baseline: 1.8936x; 1.0005x over previous
#include <cuda_runtime.h>
#include <cuda_bf16.h>
#include <cstdint>

// Problem constants
#define B_SZ   4096
#define DIN    768
#define DOUT   512
#define Q_SZ   64
#define H1_SZ  32
#define H2_SZ  64
#define EPS    1e-5f

// GEMM1 split-K: K' = 3 * DIN, A duplicated [hi|hi|lo]
#define KSPLIT (3 * DIN)          // 2304
#define KC     64
#define NCHH   (KSPLIT / KC / 2)  // 18 chunks per K-half
#define GS     3                  // pipeline stages
#define TILEB  16384              // one 128x64 bf16 tile
#define STAGEB (2 * TILEB)

// merged conv grid: conv_w blocks first (heavier), then conv_x blocks
#define CVW_BLOCKS ((DIN / 32) * (DOUT / 32))   // 384
#define CVX_BLOCKS (B_SZ * (DIN / 8) / 256)     // 4096*96/256 = 1536

// ---------------------------------------------------------------------------
// Static device scratch
// ---------------------------------------------------------------------------
__device__ __align__(256) float          g_xp[2][B_SZ * DOUT];          // 16 MB partials
__device__ __align__(256) __nv_bfloat16  g_A[B_SZ * KSPLIT];            // 18.9 MB
__device__ __align__(256) __nv_bfloat16  g_Bt[DOUT * KSPLIT];           // 2.36 MB

// ---------------------------------------------------------------------------
// Helpers
// ---------------------------------------------------------------------------
__device__ __forceinline__ uint32_t smem_u32(const void* p) {
    uint32_t a;
    asm("{ .reg .u64 t; cvta.to.shared.u64 t, %1; cvt.u32.u64 %0, t; }"
        : "=r"(a) : "l"(p));
    return a;
}
__device__ __forceinline__ uint32_t swz(uint32_t off) {
    return off ^ ((off >> 3) & 0x70);
}
__device__ __forceinline__ void cpasync16(uint32_t dst, const void* src) {
    asm volatile("cp.async.cg.shared.global [%0], [%1], 16;"
                 :: "r"(dst), "l"(src) : "memory");
}
__device__ __forceinline__ void ldsm_x4(uint32_t* r, uint32_t addr) {
    asm volatile("ldmatrix.sync.aligned.m8n8.x4.shared.b16 {%0,%1,%2,%3}, [%4];"
                 : "=r"(r[0]), "=r"(r[1]), "=r"(r[2]), "=r"(r[3]) : "r"(addr));
}
__device__ __forceinline__ void mma16816(float* d, const uint32_t* a, const uint32_t* b) {
    asm volatile(
        "mma.sync.aligned.m16n8k16.row.col.f32.bf16.bf16.f32 "
        "{%0,%1,%2,%3}, {%4,%5,%6,%7}, {%8,%9}, {%0,%1,%2,%3};"
        : "+f"(d[0]), "+f"(d[1]), "+f"(d[2]), "+f"(d[3])
        : "r"(a[0]), "r"(a[1]), "r"(a[2]), "r"(a[3]), "r"(b[0]), "r"(b[1]));
}

// ---- packed f32x2 ----
__device__ __forceinline__ uint64_t pk2(float x, float y) {
    uint64_t r; asm("mov.b64 %0,{%1,%2};" : "=l"(r) : "f"(x), "f"(y)); return r;
}
__device__ __forceinline__ void upk2(uint64_t v, float& x, float& y) {
    asm("mov.b64 {%0,%1},%2;" : "=f"(x), "=f"(y) : "l"(v));
}
__device__ __forceinline__ uint64_t fma2(uint64_t a, uint64_t b, uint64_t c) {
    uint64_t d; asm("fma.rn.f32x2 %0,%1,%2,%3;" : "=l"(d) : "l"(a), "l"(b), "l"(c));
    return d;
}
__device__ __forceinline__ uint64_t add2(uint64_t a, uint64_t b) {
    uint64_t d; asm("add.rn.f32x2 %0,%1,%2;" : "=l"(d) : "l"(a), "l"(b));
    return d;
}
__device__ __forceinline__ uint64_t abs2(uint64_t a) {
    uint64_t d; asm("and.b64 %0,%1,0x7FFFFFFF7FFFFFFF;" : "=l"(d) : "l"(a));
    return d;
}

// pack two bf16(hi-of-float) into one uint32
__device__ __forceinline__ uint32_t pack_bf2(__nv_bfloat16 a, __nv_bfloat16 b) {
    __nv_bfloat162 t;
    t.x = a; t.y = b;
    return *(uint32_t*)&t;
}

// ---------------------------------------------------------------------------
// Merged conversion kernel.
// Blocks [0, CVW_BLOCKS):  wp -> Bt = [hi ; lo ; hi]  (heavier; start first)
// Blocks [CVW_BLOCKS, +CVX_BLOCKS): x -> A = [hi | hi | lo], 1 group of 8/thread
// ---------------------------------------------------------------------------
__global__ void __launch_bounds__(256)
conv_all(const float* __restrict__ x, __nv_bfloat16* __restrict__ A,
         const float* __restrict__ wp, __nv_bfloat16* __restrict__ Bt)
{
    if (blockIdx.x >= CVW_BLOCKS) {
        // conv_x: one 8-element group per thread
        const int gid = (blockIdx.x - CVW_BLOCKS) * 256 + threadIdx.x;
        const int row = gid / 96;
        const int k0  = (gid % 96) * 8;
        const float4* xr = (const float4*)(x + (long)row * DIN + k0);
        const float4 va = xr[0];
        const float4 vb = xr[1];
        const float vv[8] = {va.x, va.y, va.z, va.w, vb.x, vb.y, vb.z, vb.w};
        uint32_t h[4], l[4];
        #pragma unroll
        for (int j = 0; j < 4; j++) {
            const float a = vv[2 * j], b = vv[2 * j + 1];
            const __nv_bfloat16 ha = __float2bfloat16(a);
            const __nv_bfloat16 hb = __float2bfloat16(b);
            h[j] = pack_bf2(ha, hb);
            l[j] = pack_bf2(__float2bfloat16(a - __bfloat162float(ha)),
                            __float2bfloat16(b - __bfloat162float(hb)));
        }
        __nv_bfloat16* Ar = A + (long)row * KSPLIT + k0;
        *(uint4*)(Ar)           = *(uint4*)h;
        *(uint4*)(Ar + DIN)     = *(uint4*)h;
        *(uint4*)(Ar + 2 * DIN) = *(uint4*)l;
    } else {
        // conv_w: 32x32 transpose tile
        __shared__ float t[32][33];
        const int bid = blockIdx.x;
        const int k0 = (bid % (DIN / 32)) * 32;
        const int n0 = (bid / (DIN / 32)) * 32;
        const int tx = threadIdx.x & 31;
        const int ty = threadIdx.x >> 5;
        #pragma unroll
        for (int dy = 0; dy < 32; dy += 8)
            t[ty + dy][tx] = wp[(long)(k0 + ty + dy) * DOUT + n0 + tx];
        __syncthreads();
        #pragma unroll
        for (int dy = 0; dy < 32; dy += 8) {
            const int n = n0 + ty + dy, k = k0 + tx;
            const float v = t[tx][ty + dy];
            const __nv_bfloat16 hi = __float2bfloat16(v);
            const __nv_bfloat16 lo = __float2bfloat16(v - __bfloat162float(hi));
            __nv_bfloat16* Br = Bt + (long)n * KSPLIT;
            Br[k]           = hi;
            Br[k + DIN]     = lo;
            Br[k + 2 * DIN] = hi;
        }
    }
}

// ---------------------------------------------------------------------------
// GEMM1, split-K=2 — unchanged (measured best)
// ---------------------------------------------------------------------------
__global__ void __launch_bounds__(256, 2)
gemm_tc(const __nv_bfloat16* __restrict__ Ag, const __nv_bfloat16* __restrict__ Bg,
        float* __restrict__ Cbase)
{
    extern __shared__ char dynsmem[];

    const int tid  = threadIdx.x;
    const int warp = tid >> 5, lane = tid & 31;
    const int wm = warp >> 2;
    const int wn = warp & 3;
    const int bn = blockIdx.x, bm = blockIdx.y, kz = blockIdx.z;

    const uint32_t abase = (smem_u32(dynsmem) + 1023u) & ~1023u;

    const __nv_bfloat16* Atile = Ag + (long)(bm * 128) * KSPLIT;
    const __nv_bfloat16* Btile = Bg + (long)(bn * 128) * KSPLIT;
    float* C = Cbase + (long)kz * (B_SZ * DOUT);
    const int kbase = kz * (NCHH * KC);

    auto load_chunk = [&](int c, int s) {
        const uint32_t sa = abase + s * STAGEB;
        const uint32_t sb = sa + TILEB;
        const int koff = kbase + c * KC;
        #pragma unroll
        for (int it = 0; it < 4; it++) {
            const int idx = it * 256 + tid;
            const int row = idx >> 3;
            const int c16 = idx & 7;
            const uint32_t soff = swz(row * 128 + c16 * 16);
            cpasync16(sa + soff, Atile + (long)row * KSPLIT + koff + c16 * 8);
            cpasync16(sb + soff, Btile + (long)row * KSPLIT + koff + c16 * 8);
        }
        asm volatile("cp.async.commit_group;" ::: "memory");
    };

    float acc[4][4][4];
    #pragma unroll
    for (int mt = 0; mt < 4; mt++)
        #pragma unroll
        for (int nt = 0; nt < 4; nt++)
            #pragma unroll
            for (int j = 0; j < 4; j++) acc[mt][nt][j] = 0.f;

    const uint32_t a_row = wm * 64 + (lane & 15);
    const uint32_t a_seg = (lane >> 4) * 16;
    const uint32_t b_row4 = wn * 32 + (lane & 7) + ((lane >> 4) << 3);
    const uint32_t b_seg4 = ((lane >> 3) & 1) * 16;

    load_chunk(0, 0);
    load_chunk(1, 1);

    int s_cons = 0, s_load = 2;
    for (int c = 0; c < NCHH; c++) {
        asm volatile("cp.async.wait_group %0;" :: "n"(GS - 2) : "memory");
        __syncthreads();

        const int nl = c + GS - 1;
        if (nl < NCHH) load_chunk(nl, s_load);
        if (++s_load == GS) s_load = 0;

        const uint32_t sa = abase + s_cons * STAGEB;
        const uint32_t sb = sa + TILEB;
        if (++s_cons == GS) s_cons = 0;

        #pragma unroll
        for (int ks = 0; ks < 4; ks++) {
            uint32_t bf[2][4];
            ldsm_x4(bf[0], sb + swz((b_row4)      * 128 + ks * 32 + b_seg4));
            ldsm_x4(bf[1], sb + swz((b_row4 + 16) * 128 + ks * 32 + b_seg4));
            #pragma unroll
            for (int mt = 0; mt < 4; mt++) {
                uint32_t af[4];
                ldsm_x4(af, sa + swz((a_row + mt * 16) * 128 + ks * 32 + a_seg));
                mma16816(acc[mt][0], af, &bf[0][0]);
                mma16816(acc[mt][1], af, &bf[0][2]);
                mma16816(acc[mt][2], af, &bf[1][0]);
                mma16816(acc[mt][3], af, &bf[1][2]);
            }
        }
    }

    const int g  = lane >> 2;
    const int tg = lane & 3;
    #pragma unroll
    for (int mt = 0; mt < 4; mt++) {
        const int m = bm * 128 + wm * 64 + mt * 16 + g;
        #pragma unroll
        for (int nt = 0; nt < 4; nt++) {
            const int n = bn * 128 + wn * 32 + nt * 8 + 2 * tg;
            float2 v0, v1;
            v0.x = acc[mt][nt][0];  v0.y = acc[mt][nt][1];
            v1.x = acc[mt][nt][2];  v1.y = acc[mt][nt][3];
            *(float2*)(C + (long)m * DOUT + n)       = v0;
            *(float2*)(C + (long)(m + 8) * DOUT + n) = v1;
        }
    }
}

// ---------------------------------------------------------------------------
// Kernel 2: scalar pipeline, R7 structure — unchanged (measured best)
// ---------------------------------------------------------------------------
#define ROWS 8

__global__ void __launch_bounds__(256)
kan_fused(const float* __restrict__ xp0, const float* __restrict__ xp1,
          const float* __restrict__ bp,
          const float* __restrict__ wi1, const float* __restrict__ bi1,
          const float* __restrict__ wi2, const float* __restrict__ bi2,
          const float* __restrict__ wo1, const float* __restrict__ bo1,
          const float* __restrict__ wo2, const float* __restrict__ bo2,
          const float* __restrict__ gamma, const float* __restrict__ beta,
          float* __restrict__ out)
{
    __shared__ float rows[ROWS][DOUT];
    __shared__ float Ssh[ROWS][H1_SZ];
    __shared__ float ush[ROWS][Q_SZ];
    __shared__ float GshT[H2_SZ][ROWS];     // transposed: [h2][r]
    __shared__ float red[ROWS][8][2];

    const int tid  = threadIdx.x;
    const int warp = tid >> 5;
    const int lane = tid & 31;
    const long base = (long)blockIdx.x * ROWS * DOUT;

    // Load 8 rows: xp0 + xp1 + bias
    {
        const float4* s0 = (const float4*)(xp0 + base);
        const float4* s1 = (const float4*)(xp1 + base);
        const float4* bb = (const float4*)bp;
        float4* dst = (float4*)(&rows[0][0]);
        #pragma unroll
        for (int i = 0; i < 4; i++) {
            const int j = tid + i * 256;
            const float4 a = s0[j];
            const float4 b = s1[j];
            const float4 c = bb[j & 127];
            float4 o;
            o.x = a.x + b.x + c.x;
            o.y = a.y + b.y + c.y;
            o.z = a.z + b.z + c.z;
            o.w = a.w + b.w + c.w;
            dst[j] = o;
        }
    }
    __syncthreads();

    // Stage B: S = 0.5*(w*V + 512*b + sum|v*w+b|)   (packed f32x2)
    {
        const float4* rv = (const float4*)(&rows[warp][0]);

        uint64_t vp = pk2(0.f, 0.f);
        #pragma unroll
        for (int i = 0; i < 4; i++) {
            const float4 v = rv[lane + i * 32];
            vp = add2(vp, pk2(v.x, v.y));
            vp = add2(vp, pk2(v.z, v.w));
        }
        float va, vb; upk2(vp, va, vb);
        float vs = va + vb;
        #pragma unroll
        for (int off = 16; off > 0; off >>= 1)
            vs += __shfl_xor_sync(0xffffffffu, vs, off);

        const float w1 = wi1[lane];
        const float b1 = bi1[lane];
        const uint64_t w11 = pk2(w1, w1);
        const uint64_t b11 = pk2(b1, b1);
        uint64_t s01 = pk2(0.f, 0.f), s23 = pk2(0.f, 0.f);
        #pragma unroll 4
        for (int d4 = 0; d4 < DOUT / 4; d4++) {
            const float4 v = rv[d4];
            s01 = add2(s01, abs2(fma2(pk2(v.x, v.y), w11, b11)));
            s23 = add2(s23, abs2(fma2(pk2(v.z, v.w), w11, b11)));
        }
        float a0, a1, a2, a3;
        upk2(s01, a0, a1); upk2(s23, a2, a3);
        const float sabs = (a0 + a1) + (a2 + a3);
        Ssh[warp][lane] = 0.5f * (fmaf(w1, vs, (float)DOUT * b1) + sabs);
    }
    __syncthreads();

    // Stage C: u[r][q]
    #pragma unroll
    for (int it = 0; it < 2; it++) {
        const int idx = tid + it * 256;
        const int r = idx >> 6, q = idx & 63;
        float acc = (float)DOUT * bi2[q];
        #pragma unroll
        for (int h = 0; h < H1_SZ; h++)
            acc = fmaf(Ssh[r][h], wi2[h * Q_SZ + q], acc);
        ush[r][q] = acc;
    }
    __syncthreads();

    // Stage D: G[r][h2] -> stored transposed
    #pragma unroll
    for (int it = 0; it < 2; it++) {
        const int idx = tid + it * 256;
        const int r = idx >> 6, h2 = idx & 63;
        const float w = wo1[h2];
        const float b = bo1[h2];
        float g = 0.f;
        #pragma unroll
        for (int q = 0; q < Q_SZ; q++)
            g += fmaxf(fmaf(ush[r][q], w, b), 0.f);
        GshT[h2][r] = g;
    }
    __syncthreads();

    // Stage E (packed f32x2): rows packed in pairs from float4 broadcasts.
    const int d0 = tid * 2;
    uint64_t acc2[8];
    #pragma unroll
    for (int j = 0; j < 8; j++) acc2[j] = pk2(0.f, 0.f);

    #pragma unroll 4
    for (int h2 = 0; h2 < H2_SZ; h2++) {
        const float2 w = *(const float2*)(wo2 + h2 * DOUT + d0);   // LDG.64
        const uint64_t wx = pk2(w.x, w.x);
        const uint64_t wy = pk2(w.y, w.y);
        const float4 ga = *(const float4*)(&GshT[h2][0]);          // rows 0-3 bcast
        const float4 gb = *(const float4*)(&GshT[h2][4]);          // rows 4-7 bcast
        const uint64_t g01 = pk2(ga.x, ga.y);
        const uint64_t g23 = pk2(ga.z, ga.w);
        const uint64_t g45 = pk2(gb.x, gb.y);
        const uint64_t g67 = pk2(gb.z, gb.w);
        acc2[0] = fma2(g01, wx, acc2[0]);
        acc2[1] = fma2(g23, wx, acc2[1]);
        acc2[2] = fma2(g45, wx, acc2[2]);
        acc2[3] = fma2(g67, wx, acc2[3]);
        acc2[4] = fma2(g01, wy, acc2[4]);
        acc2[5] = fma2(g23, wy, acc2[5]);
        acc2[6] = fma2(g45, wy, acc2[6]);
        acc2[7] = fma2(g67, wy, acc2[7]);
    }

    float ax[ROWS], ay[ROWS];
    {
        const float2 bo = *(const float2*)(bo2 + d0);
        const uint64_t bbx = pk2((float)Q_SZ * bo.x, (float)Q_SZ * bo.x);
        const uint64_t bby = pk2((float)Q_SZ * bo.y, (float)Q_SZ * bo.y);
        #pragma unroll
        for (int p = 0; p < 4; p++) {
            acc2[p]     = add2(acc2[p], bbx);
            acc2[4 + p] = add2(acc2[4 + p], bby);
            upk2(acc2[p],     ax[2 * p], ax[2 * p + 1]);
            upk2(acc2[4 + p], ay[2 * p], ay[2 * p + 1]);
        }
    }

    // LayerNorm reductions
    #pragma unroll
    for (int r = 0; r < ROWS; r++) {
        float ps = ax[r] + ay[r];
        float pq = ax[r] * ax[r] + ay[r] * ay[r];
        #pragma unroll
        for (int off = 16; off > 0; off >>= 1) {
            ps += __shfl_xor_sync(0xffffffffu, ps, off);
            pq += __shfl_xor_sync(0xffffffffu, pq, off);
        }
        if (lane == 0) { red[r][warp][0] = ps; red[r][warp][1] = pq; }
    }
    __syncthreads();

    const float2 gm = *(const float2*)(gamma + d0);
    const float2 bt = *(const float2*)(beta + d0);
    #pragma unroll
    for (int r = 0; r < ROWS; r++) {
        float s = 0.f, q2 = 0.f;
        #pragma unroll
        for (int w = 0; w < 8; w++) { s += red[r][w][0]; q2 += red[r][w][1]; }
        const float mu  = s * (1.f / (float)DOUT);
        const float var = q2 * (1.f / (float)DOUT) - mu * mu;
        const float inv = rsqrtf(var + EPS);
        float2 o;
        o.x = (ax[r] - mu) * inv * gm.x + bt.x;
        o.y = (ay[r] - mu) * inv * gm.y + bt.y;
        *(float2*)(out + base + (long)r * DOUT + d0) = o;
    }
}

// ---------------------------------------------------------------------------
// Launch
// ---------------------------------------------------------------------------
extern "C" void kernel_launch(void* const* d_in, const int* in_sizes, int n_in,
                              void* d_out, int out_size)
{
    const float* x     = (const float*)d_in[0];
    const float* wp    = (const float*)d_in[1];
    const float* bp    = (const float*)d_in[2];
    const float* wi1   = (const float*)d_in[3];
    const float* bi1   = (const float*)d_in[4];
    const float* wi2   = (const float*)d_in[5];
    const float* bi2   = (const float*)d_in[6];
    const float* wo1   = (const float*)d_in[7];
    const float* bo1   = (const float*)d_in[8];
    const float* wo2   = (const float*)d_in[9];
    const float* bo2   = (const float*)d_in[10];
    const float* gamma = (const float*)d_in[11];
    const float* beta  = (const float*)d_in[12];
    float* out = (float*)d_out;

    float* xp;             cudaGetSymbolAddress((void**)&xp, g_xp);
    __nv_bfloat16* Ab;     cudaGetSymbolAddress((void**)&Ab, g_A);
    __nv_bfloat16* Bb;     cudaGetSymbolAddress((void**)&Bb, g_Bt);

    conv_all<<<CVW_BLOCKS + CVX_BLOCKS, 256>>>(x, Ab, wp, Bb);

    const int dyn = GS * STAGEB + 1024;   // ~97 KB
    cudaFuncSetAttribute(gemm_tc, cudaFuncAttributeMaxDynamicSharedMemorySize, dyn);
    gemm_tc<<<dim3(DOUT / 128, B_SZ / 128, 2), 256, dyn>>>(Ab, Bb, xp);

    kan_fused<<<B_SZ / ROWS, 256>>>(xp, xp + (long)B_SZ * DOUT, bp,
                                    wi1, bi1, wi2, bi2,
                                    wo1, bo1, wo2, bo2, gamma, beta, out);
}

// round 17
// speedup vs baseline: 2.1938x; 1.1585x over previous
#include <cuda_runtime.h>
#include <cuda_fp16.h>
#include <cuda_bf16.h>
#include <cstdint>

// Problem constants
#define B_SZ   4096
#define DIN    768
#define DOUT   512
#define Q_SZ   64
#define H1_SZ  32
#define H2_SZ  64
#define EPS    1e-5f

// GEMM1: 2-term fp16 compensated split, K' = 2 * DIN
// A = [x_hi | x_lo] (fp16), B = [w_hi ; w_hi]  ->  (x_hi+x_lo)@w_hi ~= x@w
#define KF     (2 * DIN)          // 1536
#define KC     64
#define NCHH   (KF / KC / 2)      // 12 chunks per K-half (split-K=2)
#define GS     3                  // pipeline stages
#define TILEB  16384              // one 128x64 fp16 tile (128B rows)
#define STAGEB (2 * TILEB)

// merged conv grid: conv_w blocks first (heavier), then conv_x blocks
#define CVW_BLOCKS ((DIN / 32) * (DOUT / 32))   // 384
#define CVX_BLOCKS (B_SZ * (DIN / 8) / 256)     // 1536

// ---------------------------------------------------------------------------
// Static device scratch
// ---------------------------------------------------------------------------
__device__ __align__(256) float   g_xp[2][B_SZ * DOUT];    // 16 MB partials
__device__ __align__(256) __half  g_A[B_SZ * KF];          // 12.6 MB
__device__ __align__(256) __half  g_Bt[DOUT * KF];         // 1.6 MB

// ---------------------------------------------------------------------------
// Helpers
// ---------------------------------------------------------------------------
__device__ __forceinline__ uint32_t smem_u32(const void* p) {
    uint32_t a;
    asm("{ .reg .u64 t; cvta.to.shared.u64 t, %1; cvt.u32.u64 %0, t; }"
        : "=r"(a) : "l"(p));
    return a;
}
__device__ __forceinline__ uint32_t swz(uint32_t off) {
    return off ^ ((off >> 3) & 0x70);
}
__device__ __forceinline__ void cpasync16(uint32_t dst, const void* src) {
    asm volatile("cp.async.cg.shared.global [%0], [%1], 16;"
                 :: "r"(dst), "l"(src) : "memory");
}
__device__ __forceinline__ void ldsm_x4(uint32_t* r, uint32_t addr) {
    asm volatile("ldmatrix.sync.aligned.m8n8.x4.shared.b16 {%0,%1,%2,%3}, [%4];"
                 : "=r"(r[0]), "=r"(r[1]), "=r"(r[2]), "=r"(r[3]) : "r"(addr));
}
__device__ __forceinline__ void mma16816h(float* d, const uint32_t* a, const uint32_t* b) {
    asm volatile(
        "mma.sync.aligned.m16n8k16.row.col.f32.f16.f16.f32 "
        "{%0,%1,%2,%3}, {%4,%5,%6,%7}, {%8,%9}, {%0,%1,%2,%3};"
        : "+f"(d[0]), "+f"(d[1]), "+f"(d[2]), "+f"(d[3])
        : "r"(a[0]), "r"(a[1]), "r"(a[2]), "r"(a[3]), "r"(b[0]), "r"(b[1]));
}

// ---- packed f32x2 ----
__device__ __forceinline__ uint64_t pk2(float x, float y) {
    uint64_t r; asm("mov.b64 %0,{%1,%2};" : "=l"(r) : "f"(x), "f"(y)); return r;
}
__device__ __forceinline__ void upk2(uint64_t v, float& x, float& y) {
    asm("mov.b64 {%0,%1},%2;" : "=f"(x), "=f"(y) : "l"(v));
}
__device__ __forceinline__ uint64_t fma2(uint64_t a, uint64_t b, uint64_t c) {
    uint64_t d; asm("fma.rn.f32x2 %0,%1,%2,%3;" : "=l"(d) : "l"(a), "l"(b), "l"(c));
    return d;
}
__device__ __forceinline__ uint64_t add2(uint64_t a, uint64_t b) {
    uint64_t d; asm("add.rn.f32x2 %0,%1,%2;" : "=l"(d) : "l"(a), "l"(b));
    return d;
}
__device__ __forceinline__ uint64_t abs2(uint64_t a) {
    uint64_t d; asm("and.b64 %0,%1,0x7FFFFFFF7FFFFFFF;" : "=l"(d) : "l"(a));
    return d;
}

// pack two fp16 into one uint32
__device__ __forceinline__ uint32_t pack_h2(__half a, __half b) {
    __half2 t;
    t.x = a; t.y = b;
    return *(uint32_t*)&t;
}

// ---------------------------------------------------------------------------
// Merged conversion kernel.
// Blocks [0, CVW_BLOCKS):  wp -> Bt = [hi ; hi]  (fp16; heavier, start first)
// Blocks [CVW_BLOCKS, +CVX_BLOCKS): x -> A = [hi | lo] fp16, 8 elems/thread
// ---------------------------------------------------------------------------
__global__ void __launch_bounds__(256)
conv_all(const float* __restrict__ x, __half* __restrict__ A,
         const float* __restrict__ wp, __half* __restrict__ Bt)
{
    if (blockIdx.x >= CVW_BLOCKS) {
        const int gid = (blockIdx.x - CVW_BLOCKS) * 256 + threadIdx.x;
        const int row = gid / 96;
        const int k0  = (gid % 96) * 8;
        const float4* xr = (const float4*)(x + (long)row * DIN + k0);
        const float4 va = xr[0];
        const float4 vb = xr[1];
        const float vv[8] = {va.x, va.y, va.z, va.w, vb.x, vb.y, vb.z, vb.w};
        uint32_t h[4], l[4];
        #pragma unroll
        for (int j = 0; j < 4; j++) {
            const float a = vv[2 * j], b = vv[2 * j + 1];
            const __half ha = __float2half_rn(a);
            const __half hb = __float2half_rn(b);
            h[j] = pack_h2(ha, hb);
            l[j] = pack_h2(__float2half_rn(a - __half2float(ha)),
                           __float2half_rn(b - __half2float(hb)));
        }
        __half* Ar = A + (long)row * KF + k0;
        *(uint4*)(Ar)       = *(uint4*)h;
        *(uint4*)(Ar + DIN) = *(uint4*)l;
    } else {
        // conv_w: 32x32 transpose tile; both K-regions get w_hi
        __shared__ float t[32][33];
        const int bid = blockIdx.x;
        const int k0 = (bid % (DIN / 32)) * 32;
        const int n0 = (bid / (DIN / 32)) * 32;
        const int tx = threadIdx.x & 31;
        const int ty = threadIdx.x >> 5;
        #pragma unroll
        for (int dy = 0; dy < 32; dy += 8)
            t[ty + dy][tx] = wp[(long)(k0 + ty + dy) * DOUT + n0 + tx];
        __syncthreads();
        #pragma unroll
        for (int dy = 0; dy < 32; dy += 8) {
            const int n = n0 + ty + dy, k = k0 + tx;
            const __half hi = __float2half_rn(t[tx][ty + dy]);
            __half* Br = Bt + (long)n * KF;
            Br[k]       = hi;
            Br[k + DIN] = hi;
        }
    }
}

// ---------------------------------------------------------------------------
// GEMM1 (fp16 HMMA), split-K=2: same tile structure as the validated bf16 path
// (identical byte layout: 64 fp16 = 128B rows, SW128 swizzle, ldsm b16).
// ---------------------------------------------------------------------------
__global__ void __launch_bounds__(256, 2)
gemm_tc(const __half* __restrict__ Ag, const __half* __restrict__ Bg,
        float* __restrict__ Cbase)
{
    extern __shared__ char dynsmem[];

    const int tid  = threadIdx.x;
    const int warp = tid >> 5, lane = tid & 31;
    const int wm = warp >> 2;
    const int wn = warp & 3;
    const int bn = blockIdx.x, bm = blockIdx.y, kz = blockIdx.z;

    const uint32_t abase = (smem_u32(dynsmem) + 1023u) & ~1023u;

    const __half* Atile = Ag + (long)(bm * 128) * KF;
    const __half* Btile = Bg + (long)(bn * 128) * KF;
    float* C = Cbase + (long)kz * (B_SZ * DOUT);
    const int kbase = kz * (NCHH * KC);

    auto load_chunk = [&](int c, int s) {
        const uint32_t sa = abase + s * STAGEB;
        const uint32_t sb = sa + TILEB;
        const int koff = kbase + c * KC;
        #pragma unroll
        for (int it = 0; it < 4; it++) {
            const int idx = it * 256 + tid;
            const int row = idx >> 3;
            const int c16 = idx & 7;
            const uint32_t soff = swz(row * 128 + c16 * 16);
            cpasync16(sa + soff, Atile + (long)row * KF + koff + c16 * 8);
            cpasync16(sb + soff, Btile + (long)row * KF + koff + c16 * 8);
        }
        asm volatile("cp.async.commit_group;" ::: "memory");
    };

    float acc[4][4][4];
    #pragma unroll
    for (int mt = 0; mt < 4; mt++)
        #pragma unroll
        for (int nt = 0; nt < 4; nt++)
            #pragma unroll
            for (int j = 0; j < 4; j++) acc[mt][nt][j] = 0.f;

    const uint32_t a_row = wm * 64 + (lane & 15);
    const uint32_t a_seg = (lane >> 4) * 16;
    const uint32_t b_row4 = wn * 32 + (lane & 7) + ((lane >> 4) << 3);
    const uint32_t b_seg4 = ((lane >> 3) & 1) * 16;

    load_chunk(0, 0);
    load_chunk(1, 1);

    int s_cons = 0, s_load = 2;
    for (int c = 0; c < NCHH; c++) {
        asm volatile("cp.async.wait_group %0;" :: "n"(GS - 2) : "memory");
        __syncthreads();

        const int nl = c + GS - 1;
        if (nl < NCHH) load_chunk(nl, s_load);
        if (++s_load == GS) s_load = 0;

        const uint32_t sa = abase + s_cons * STAGEB;
        const uint32_t sb = sa + TILEB;
        if (++s_cons == GS) s_cons = 0;

        #pragma unroll
        for (int ks = 0; ks < 4; ks++) {
            uint32_t bf[2][4];
            ldsm_x4(bf[0], sb + swz((b_row4)      * 128 + ks * 32 + b_seg4));
            ldsm_x4(bf[1], sb + swz((b_row4 + 16) * 128 + ks * 32 + b_seg4));
            #pragma unroll
            for (int mt = 0; mt < 4; mt++) {
                uint32_t af[4];
                ldsm_x4(af, sa + swz((a_row + mt * 16) * 128 + ks * 32 + a_seg));
                mma16816h(acc[mt][0], af, &bf[0][0]);
                mma16816h(acc[mt][1], af, &bf[0][2]);
                mma16816h(acc[mt][2], af, &bf[1][0]);
                mma16816h(acc[mt][3], af, &bf[1][2]);
            }
        }
    }

    const int g  = lane >> 2;
    const int tg = lane & 3;
    #pragma unroll
    for (int mt = 0; mt < 4; mt++) {
        const int m = bm * 128 + wm * 64 + mt * 16 + g;
        #pragma unroll
        for (int nt = 0; nt < 4; nt++) {
            const int n = bn * 128 + wn * 32 + nt * 8 + 2 * tg;
            float2 v0, v1;
            v0.x = acc[mt][nt][0];  v0.y = acc[mt][nt][1];
            v1.x = acc[mt][nt][2];  v1.y = acc[mt][nt][3];
            *(float2*)(C + (long)m * DOUT + n)       = v0;
            *(float2*)(C + (long)(m + 8) * DOUT + n) = v1;
        }
    }
}

// ---------------------------------------------------------------------------
// Kernel 2: scalar pipeline, R7 structure — unchanged (measured best)
// ---------------------------------------------------------------------------
#define ROWS 8

__global__ void __launch_bounds__(256)
kan_fused(const float* __restrict__ xp0, const float* __restrict__ xp1,
          const float* __restrict__ bp,
          const float* __restrict__ wi1, const float* __restrict__ bi1,
          const float* __restrict__ wi2, const float* __restrict__ bi2,
          const float* __restrict__ wo1, const float* __restrict__ bo1,
          const float* __restrict__ wo2, const float* __restrict__ bo2,
          const float* __restrict__ gamma, const float* __restrict__ beta,
          float* __restrict__ out)
{
    __shared__ float rows[ROWS][DOUT];
    __shared__ float Ssh[ROWS][H1_SZ];
    __shared__ float ush[ROWS][Q_SZ];
    __shared__ float GshT[H2_SZ][ROWS];     // transposed: [h2][r]
    __shared__ float red[ROWS][8][2];

    const int tid  = threadIdx.x;
    const int warp = tid >> 5;
    const int lane = tid & 31;
    const long base = (long)blockIdx.x * ROWS * DOUT;

    // Load 8 rows: xp0 + xp1 + bias
    {
        const float4* s0 = (const float4*)(xp0 + base);
        const float4* s1 = (const float4*)(xp1 + base);
        const float4* bb = (const float4*)bp;
        float4* dst = (float4*)(&rows[0][0]);
        #pragma unroll
        for (int i = 0; i < 4; i++) {
            const int j = tid + i * 256;
            const float4 a = s0[j];
            const float4 b = s1[j];
            const float4 c = bb[j & 127];
            float4 o;
            o.x = a.x + b.x + c.x;
            o.y = a.y + b.y + c.y;
            o.z = a.z + b.z + c.z;
            o.w = a.w + b.w + c.w;
            dst[j] = o;
        }
    }
    __syncthreads();

    // Stage B: S = 0.5*(w*V + 512*b + sum|v*w+b|)   (packed f32x2)
    {
        const float4* rv = (const float4*)(&rows[warp][0]);

        uint64_t vp = pk2(0.f, 0.f);
        #pragma unroll
        for (int i = 0; i < 4; i++) {
            const float4 v = rv[lane + i * 32];
            vp = add2(vp, pk2(v.x, v.y));
            vp = add2(vp, pk2(v.z, v.w));
        }
        float va, vb; upk2(vp, va, vb);
        float vs = va + vb;
        #pragma unroll
        for (int off = 16; off > 0; off >>= 1)
            vs += __shfl_xor_sync(0xffffffffu, vs, off);

        const float w1 = wi1[lane];
        const float b1 = bi1[lane];
        const uint64_t w11 = pk2(w1, w1);
        const uint64_t b11 = pk2(b1, b1);
        uint64_t s01 = pk2(0.f, 0.f), s23 = pk2(0.f, 0.f);
        #pragma unroll 4
        for (int d4 = 0; d4 < DOUT / 4; d4++) {
            const float4 v = rv[d4];
            s01 = add2(s01, abs2(fma2(pk2(v.x, v.y), w11, b11)));
            s23 = add2(s23, abs2(fma2(pk2(v.z, v.w), w11, b11)));
        }
        float a0, a1, a2, a3;
        upk2(s01, a0, a1); upk2(s23, a2, a3);
        const float sabs = (a0 + a1) + (a2 + a3);
        Ssh[warp][lane] = 0.5f * (fmaf(w1, vs, (float)DOUT * b1) + sabs);
    }
    __syncthreads();

    // Stage C: u[r][q]
    #pragma unroll
    for (int it = 0; it < 2; it++) {
        const int idx = tid + it * 256;
        const int r = idx >> 6, q = idx & 63;
        float acc = (float)DOUT * bi2[q];
        #pragma unroll
        for (int h = 0; h < H1_SZ; h++)
            acc = fmaf(Ssh[r][h], wi2[h * Q_SZ + q], acc);
        ush[r][q] = acc;
    }
    __syncthreads();

    // Stage D: G[r][h2] -> stored transposed
    #pragma unroll
    for (int it = 0; it < 2; it++) {
        const int idx = tid + it * 256;
        const int r = idx >> 6, h2 = idx & 63;
        const float w = wo1[h2];
        const float b = bo1[h2];
        float g = 0.f;
        #pragma unroll
        for (int q = 0; q < Q_SZ; q++)
            g += fmaxf(fmaf(ush[r][q], w, b), 0.f);
        GshT[h2][r] = g;
    }
    __syncthreads();

    // Stage E (packed f32x2): rows packed in pairs from float4 broadcasts.
    const int d0 = tid * 2;
    uint64_t acc2[8];
    #pragma unroll
    for (int j = 0; j < 8; j++) acc2[j] = pk2(0.f, 0.f);

    #pragma unroll 4
    for (int h2 = 0; h2 < H2_SZ; h2++) {
        const float2 w = *(const float2*)(wo2 + h2 * DOUT + d0);   // LDG.64
        const uint64_t wx = pk2(w.x, w.x);
        const uint64_t wy = pk2(w.y, w.y);
        const float4 ga = *(const float4*)(&GshT[h2][0]);          // rows 0-3 bcast
        const float4 gb = *(const float4*)(&GshT[h2][4]);          // rows 4-7 bcast
        const uint64_t g01 = pk2(ga.x, ga.y);
        const uint64_t g23 = pk2(ga.z, ga.w);
        const uint64_t g45 = pk2(gb.x, gb.y);
        const uint64_t g67 = pk2(gb.z, gb.w);
        acc2[0] = fma2(g01, wx, acc2[0]);
        acc2[1] = fma2(g23, wx, acc2[1]);
        acc2[2] = fma2(g45, wx, acc2[2]);
        acc2[3] = fma2(g67, wx, acc2[3]);
        acc2[4] = fma2(g01, wy, acc2[4]);
        acc2[5] = fma2(g23, wy, acc2[5]);
        acc2[6] = fma2(g45, wy, acc2[6]);
        acc2[7] = fma2(g67, wy, acc2[7]);
    }

    float ax[ROWS], ay[ROWS];
    {
        const float2 bo = *(const float2*)(bo2 + d0);
        const uint64_t bbx = pk2((float)Q_SZ * bo.x, (float)Q_SZ * bo.x);
        const uint64_t bby = pk2((float)Q_SZ * bo.y, (float)Q_SZ * bo.y);
        #pragma unroll
        for (int p = 0; p < 4; p++) {
            acc2[p]     = add2(acc2[p], bbx);
            acc2[4 + p] = add2(acc2[4 + p], bby);
            upk2(acc2[p],     ax[2 * p], ax[2 * p + 1]);
            upk2(acc2[4 + p], ay[2 * p], ay[2 * p + 1]);
        }
    }

    // LayerNorm reductions
    #pragma unroll
    for (int r = 0; r < ROWS; r++) {
        float ps = ax[r] + ay[r];
        float pq = ax[r] * ax[r] + ay[r] * ay[r];
        #pragma unroll
        for (int off = 16; off > 0; off >>= 1) {
            ps += __shfl_xor_sync(0xffffffffu, ps, off);
            pq += __shfl_xor_sync(0xffffffffu, pq, off);
        }
        if (lane == 0) { red[r][warp][0] = ps; red[r][warp][1] = pq; }
    }
    __syncthreads();

    const float2 gm = *(const float2*)(gamma + d0);
    const float2 bt = *(const float2*)(beta + d0);
    #pragma unroll
    for (int r = 0; r < ROWS; r++) {
        float s = 0.f, q2 = 0.f;
        #pragma unroll
        for (int w = 0; w < 8; w++) { s += red[r][w][0]; q2 += red[r][w][1]; }
        const float mu  = s * (1.f / (float)DOUT);
        const float var = q2 * (1.f / (float)DOUT) - mu * mu;
        const float inv = rsqrtf(var + EPS);
        float2 o;
        o.x = (ax[r] - mu) * inv * gm.x + bt.x;
        o.y = (ay[r] - mu) * inv * gm.y + bt.y;
        *(float2*)(out + base + (long)r * DOUT + d0) = o;
    }
}

// ---------------------------------------------------------------------------
// Launch
// ---------------------------------------------------------------------------
extern "C" void kernel_launch(void* const* d_in, const int* in_sizes, int n_in,
                              void* d_out, int out_size)
{
    const float* x     = (const float*)d_in[0];
    const float* wp    = (const float*)d_in[1];
    const float* bp    = (const float*)d_in[2];
    const float* wi1   = (const float*)d_in[3];
    const float* bi1   = (const float*)d_in[4];
    const float* wi2   = (const float*)d_in[5];
    const float* bi2   = (const float*)d_in[6];
    const float* wo1   = (const float*)d_in[7];
    const float* bo1   = (const float*)d_in[8];
    const float* wo2   = (const float*)d_in[9];
    const float* bo2   = (const float*)d_in[10];
    const float* gamma = (const float*)d_in[11];
    const float* beta  = (const float*)d_in[12];
    float* out = (float*)d_out;

    float* xp;        cudaGetSymbolAddress((void**)&xp, g_xp);
    __half* Ab;       cudaGetSymbolAddress((void**)&Ab, g_A);
    __half* Bb;       cudaGetSymbolAddress((void**)&Bb, g_Bt);

    conv_all<<<CVW_BLOCKS + CVX_BLOCKS, 256>>>(x, Ab, wp, Bb);

    const int dyn = GS * STAGEB + 1024;   // ~97 KB
    cudaFuncSetAttribute(gemm_tc, cudaFuncAttributeMaxDynamicSharedMemorySize, dyn);
    gemm_tc<<<dim3(DOUT / 128, B_SZ / 128, 2), 256, dyn>>>(Ab, Bb, xp);

    kan_fused<<<B_SZ / ROWS, 256>>>(xp, xp + (long)B_SZ * DOUT, bp,
                                    wi1, bi1, wi2, bi2,
                                    wo1, bo1, wo2, bo2, gamma, beta, out);
}